// round 14
// baseline (speedup 1.0000x reference)
#include <cuda_runtime.h>
#include <cuda_bf16.h>
#include <math.h>

// ---------------- problem constants ----------------
#define DIMC    96
#define NHC     3
#define HEADC   32
#define WSC     7
#define SHIFTC  3
#define PC      5
#define HC      56
#define NWC     64
#define TPC     320
#define NNC     54
#define BATCHC  64
#define TOKC    3456
#define MROWS   (BATCHC * NWC * NNC)   // 221184
#define HIDC    384
#define SCALEC  0.17677669529663687f

// ---------------- scratch ----------------
__device__ float               g_qkv     [(size_t)MROWS * 3 * DIMC];
__device__ __align__(16) uint2 g_attno_sp[MROWS * 48];            // attn out, window order
__device__ float               g_y       [MROWS * DIMC];          // residual stream (fp32)
// pre-split weights [kpair][n]
__device__ __align__(16) uint2 g_wq_sp[48 * 288];
__device__ __align__(16) uint2 g_wp_sp[48 * 96];
__device__ __align__(16) uint2 g_w1_sp[48 * 384];
__device__ __align__(16) uint2 g_w2_sp[192 * 96];

__device__ __forceinline__ int map_token(int bw, int n) {
    int b = bw >> 6;
    int w = bw & 63;
    int tok;
    if (n < PC) {
        tok = w * PC + n;
    } else {
        int p  = n - PC;
        int r  = p / 7, c = p % 7;
        int wh = w >> 3, ww = w & 7;
        int hr = wh * 7 + r + SHIFTC; if (hr >= HC) hr -= HC;
        int wc = ww * 7 + c + SHIFTC; if (wc >= HC) wc -= HC;
        tok = TPC + hr * HC + wc;
    }
    return b * TOKC + tok;
}

__device__ __forceinline__ float warp_sum(float v) {
    #pragma unroll
    for (int o = 16; o; o >>= 1) v += __shfl_xor_sync(0xffffffffu, v, o);
    return v;
}

__device__ __forceinline__ uint2 split_bf16_pair(float x0, float x1) {
    __nv_bfloat16 h0 = __float2bfloat16(x0);
    __nv_bfloat16 h1 = __float2bfloat16(x1);
    float r0 = x0 - __bfloat162float(h0);
    float r1 = x1 - __bfloat162float(h1);
    __nv_bfloat16 l0 = __float2bfloat16(r0);
    __nv_bfloat16 l1 = __float2bfloat16(r1);
    uint2 o;
    o.x = ((unsigned)__bfloat16_as_ushort(h1) << 16) | (unsigned)__bfloat16_as_ushort(h0);
    o.y = ((unsigned)__bfloat16_as_ushort(l1) << 16) | (unsigned)__bfloat16_as_ushort(l0);
    return o;
}

// ---- packed f32x2 helpers ----
__device__ __forceinline__ unsigned long long pack2(float lo, float hi) {
    unsigned long long d;
    asm("mov.b64 %0, {%1, %2};" : "=l"(d) : "f"(lo), "f"(hi));
    return d;
}
__device__ __forceinline__ void unpack2(float& lo, float& hi, unsigned long long v) {
    asm("mov.b64 {%0, %1}, %2;" : "=f"(lo), "=f"(hi) : "l"(v));
}
__device__ __forceinline__ unsigned long long fma2(unsigned long long a, unsigned long long b,
                                                   unsigned long long c) {
    unsigned long long d;
    asm("fma.rn.f32x2 %0, %1, %2, %3;" : "=l"(d) : "l"(a), "l"(b), "l"(c));
    return d;
}
__device__ __forceinline__ unsigned long long add2(unsigned long long a, unsigned long long b) {
    unsigned long long d;
    asm("add.rn.f32x2 %0, %1, %2;" : "=l"(d) : "l"(a), "l"(b));
    return d;
}
__device__ __forceinline__ unsigned long long mul2(unsigned long long a, unsigned long long b) {
    unsigned long long d;
    asm("mul.rn.f32x2 %0, %1, %2;" : "=l"(d) : "l"(a), "l"(b));
    return d;
}

// ---------------- weight pre-split ----------------
__global__ __launch_bounds__(256)
void split_w_kernel(const float* __restrict__ qkv_w, const float* __restrict__ proj_w,
                    const float* __restrict__ fc1_w, const float* __restrict__ fc2_w) {
    int i = blockIdx.x * blockDim.x + threadIdx.x;
    if (i < 13824) {
        int kp = i / 288, n = i % 288;
        g_wq_sp[i] = split_bf16_pair(qkv_w[(2 * kp) * 288 + n], qkv_w[(2 * kp + 1) * 288 + n]);
    } else if (i < 18432) {
        int j = i - 13824, kp = j / 96, n = j % 96;
        g_wp_sp[j] = split_bf16_pair(proj_w[(2 * kp) * 96 + n], proj_w[(2 * kp + 1) * 96 + n]);
    } else if (i < 36864) {
        int j = i - 18432, kp = j / 384, n = j % 384;
        g_w1_sp[j] = split_bf16_pair(fc1_w[(2 * kp) * 384 + n], fc1_w[(2 * kp + 1) * 384 + n]);
    } else if (i < 55296) {
        int j = i - 36864, kp = j / 96, n = j % 96;
        g_w2_sp[j] = split_bf16_pair(fc2_w[(2 * kp) * 96 + n], fc2_w[(2 * kp + 1) * 96 + n]);
    }
}

// ---------------- BF16x3 MMA primitive ----------------
__device__ __forceinline__ void mma16(float c[4],
                                      unsigned a0, unsigned a1, unsigned a2, unsigned a3,
                                      unsigned b0, unsigned b1) {
    asm volatile("mma.sync.aligned.m16n8k16.row.col.f32.bf16.bf16.f32 "
                 "{%0,%1,%2,%3}, {%4,%5,%6,%7}, {%8,%9}, {%0,%1,%2,%3};\n"
                 : "+f"(c[0]), "+f"(c[1]), "+f"(c[2]), "+f"(c[3])
                 : "r"(a0), "r"(a1), "r"(a2), "r"(a3), "r"(b0), "r"(b1));
}

// LN a 64-row fp32 smem tile [64][98] into split pairs AsF[kpair][row]. 8 warps x 8 rows.
__device__ __forceinline__ void ln_tile_to_asf(const float* ytmp, uint2 (*AsF)[68],
                                               const float* __restrict__ lng,
                                               const float* __restrict__ lnb,
                                               int wid, int lane) {
    const float2* g2 = (const float2*)lng;
    const float2* b2 = (const float2*)lnb;
    float2 G0 = g2[lane], B0 = b2[lane];
    float2 G1 = make_float2(0.f, 0.f), B1 = make_float2(0.f, 0.f);
    if (lane < 16) { G1 = g2[32 + lane]; B1 = b2[32 + lane]; }
    #pragma unroll
    for (int rr = 0; rr < 8; rr++) {
        int r = wid * 8 + rr;
        float2 a0 = *(const float2*)&ytmp[r * 98 + 2 * lane];
        float2 a1 = make_float2(0.f, 0.f);
        if (lane < 16) a1 = *(const float2*)&ytmp[r * 98 + 64 + 2 * lane];
        float s = a0.x + a0.y + a1.x + a1.y;
        float mean = warp_sum(s) * (1.f / 96.f);
        float d0x = a0.x - mean, d0y = a0.y - mean;
        float d1x = a1.x - mean, d1y = a1.y - mean;
        float vq = d0x * d0x + d0y * d0y + (lane < 16 ? d1x * d1x + d1y * d1y : 0.f);
        float var = warp_sum(vq) * (1.f / 96.f);
        float inv = rsqrtf(var + 1e-5f);
        AsF[lane][r] = split_bf16_pair(d0x * inv * G0.x + B0.x, d0y * inv * G0.y + B0.y);
        if (lane < 16)
            AsF[32 + lane][r] = split_bf16_pair(d1x * inv * G1.x + B1.x, d1y * inv * G1.y + B1.y);
    }
}

// ---------------- QKV GEMM with fused LN1 + shifted-window gather ----------------
#define QKV_ASF  (48 * 68)
#define QKV_BS   (48 * 100)
#define QKV_SMEM ((QKV_ASF + QKV_BS) * 8)   // 64512 bytes

__global__ __launch_bounds__(256, 2)
void qkv_kernel(const float* __restrict__ x,
                const float* __restrict__ lng, const float* __restrict__ lnb,
                const uint2* __restrict__ W,
                const float* __restrict__ bias,
                float* __restrict__ out) {
    extern __shared__ uint2 smemu[];
    uint2 (*AsF)[68] = reinterpret_cast<uint2(*)[68]>(smemu);
    uint2 (*Bs)[100] = reinterpret_cast<uint2(*)[100]>(smemu + QKV_ASF);
    float* ytmp = (float*)(smemu + QKV_ASF);   // aliases Bs region (25 KB <= 38.4 KB)
    __shared__ int toks[64];

    const int tid  = threadIdx.x;
    const int wid  = tid >> 5, lane = tid & 31;
    const int gid  = lane >> 2, tig = lane & 3;
    const int wm   = (wid >> 2) * 32;
    const int wn   = (wid & 3) * 24;
    const int m0   = blockIdx.x * 64;

    // ---- prologue: gather x rows, LN1, write split pairs into AsF ----
    if (tid < 64) {
        int r = m0 + tid;
        toks[tid] = map_token(r / NNC, r % NNC);
    }
    __syncthreads();
    #pragma unroll
    for (int j = 0; j < 12; j++) {                 // 64 rows x 48 float2
        int c   = tid + 256 * j;
        int row = c / 48, cp = c % 48;
        float2 v = *(const float2*)(x + (size_t)toks[row] * DIMC + 2 * cp);
        *(float2*)&ytmp[row * 98 + 2 * cp] = v;
    }
    __syncthreads();
    ln_tile_to_asf(ytmp, AsF, lng, lnb, wid, lane);

    for (int cc = 0; cc < 3; cc++) {
        __syncthreads();   // LN done for all warps (cc=0) / Bs reads done (cc>0)

        #pragma unroll
        for (int j = 0; j < 9; j++) {
            int c2 = tid + 256 * j;
            int kp = c2 / 48;
            int n2 = (c2 % 48) * 2;
            uint4 v = *(const uint4*)(W + (size_t)kp * 288 + cc * 96 + n2);
            *(uint4*)&Bs[kp][n2] = v;
        }
        __syncthreads();

        float acc[2][3][4];
        #pragma unroll
        for (int i = 0; i < 2; i++)
            #pragma unroll
            for (int j = 0; j < 3; j++)
                #pragma unroll
                for (int r = 0; r < 4; r++) acc[i][j][r] = 0.f;

        #pragma unroll
        for (int kt = 0; kt < 6; kt++) {
            const int kb = kt * 8;
            uint2 af[2][4];
            #pragma unroll
            for (int mt = 0; mt < 2; mt++) {
                const int m = wm + mt * 16 + gid;
                af[mt][0] = AsF[kb + tig    ][m];
                af[mt][1] = AsF[kb + tig    ][m + 8];
                af[mt][2] = AsF[kb + tig + 4][m];
                af[mt][3] = AsF[kb + tig + 4][m + 8];
            }
            uint2 bf[3][2];
            #pragma unroll
            for (int nt = 0; nt < 3; nt++) {
                const int n = wn + nt * 8 + gid;
                bf[nt][0] = Bs[kb + tig    ][n];
                bf[nt][1] = Bs[kb + tig + 4][n];
            }
            #pragma unroll
            for (int mt = 0; mt < 2; mt++)
                #pragma unroll
                for (int nt = 0; nt < 3; nt++) {
                    float* c = acc[mt][nt];
                    mma16(c, af[mt][0].x, af[mt][1].x, af[mt][2].x, af[mt][3].x,
                             bf[nt][0].x, bf[nt][1].x);
                    mma16(c, af[mt][0].x, af[mt][1].x, af[mt][2].x, af[mt][3].x,
                             bf[nt][0].y, bf[nt][1].y);
                    mma16(c, af[mt][0].y, af[mt][1].y, af[mt][2].y, af[mt][3].y,
                             bf[nt][0].x, bf[nt][1].x);
                }
        }

        float bb[3][2];
        #pragma unroll
        for (int nt = 0; nt < 3; nt++) {
            int c = cc * 96 + wn + nt * 8 + tig * 2;
            bb[nt][0] = bias[c];
            bb[nt][1] = bias[c + 1];
        }
        #pragma unroll
        for (int mt = 0; mt < 2; mt++) {
            #pragma unroll
            for (int half = 0; half < 2; half++) {
                size_t rg = (size_t)(m0 + wm + mt * 16 + gid + half * 8);
                float* op = out + rg * 288 + cc * 96 + wn + tig * 2;
                #pragma unroll
                for (int nt = 0; nt < 3; nt++) {
                    float v0 = acc[mt][nt][half * 2 + 0] + bb[nt][0];
                    float v1 = acc[mt][nt][half * 2 + 1] + bb[nt][1];
                    *(float2*)(op + nt * 8) = make_float2(v0, v1);
                }
            }
        }
    }
}

// ---------------- proj GEMM (unchanged) ----------------
#define GEMM_SMEM ((2 * 16 * 132 + 2 * 16 * 100) * 8)   // 59392 bytes

__global__ __launch_bounds__(256, 2)
void proj_gemm(const uint2* __restrict__ A, const uint2* __restrict__ Bw,
               const float* __restrict__ bias, const float* __restrict__ res,
               float* __restrict__ out) {
    const int N = 96, K = 96, KP = 48;
    extern __shared__ uint2 smemu[];
    uint2 (*As2)[16][132] = reinterpret_cast<uint2(*)[16][132]>(smemu);
    uint2 (*Bs2)[16][100] = reinterpret_cast<uint2(*)[16][100]>(smemu + 2 * 16 * 132);

    const int tid  = threadIdx.x;
    const int wid  = tid >> 5, lane = tid & 31;
    const int gid  = lane >> 2, tig = lane & 3;
    const int wm   = (wid >> 1) * 32;
    const int wn   = (wid & 1) * 48;
    const int m0   = blockIdx.y * 128;

    int arow[4], akp[4];
    const uint2* aPtr[4];
    #pragma unroll
    for (int j = 0; j < 4; j++) {
        int c = tid + 256 * j;
        arow[j] = c >> 3;
        akp[j]  = (c & 7) * 2;
        aPtr[j] = A + (size_t)(m0 + arow[j]) * KP + akp[j];
    }
    int bkp[3], bn2[3];
    const uint2* bPtr[3];
    #pragma unroll
    for (int j = 0; j < 3; j++) {
        int c = tid + 256 * j;
        bkp[j] = c / 48;
        bn2[j] = (c % 48) * 2;
        bPtr[j] = Bw + (size_t)bkp[j] * N + bn2[j];
    }

    float acc[2][6][4];
    #pragma unroll
    for (int i = 0; i < 2; i++)
        #pragma unroll
        for (int j = 0; j < 6; j++)
            #pragma unroll
            for (int r = 0; r < 4; r++) acc[i][j][r] = 0.f;

    uint4 aR[4], bR[3];
    #pragma unroll
    for (int j = 0; j < 4; j++) aR[j] = *(const uint4*)(aPtr[j]);
    #pragma unroll
    for (int j = 0; j < 3; j++) bR[j] = *(const uint4*)(bPtr[j]);

    #pragma unroll
    for (int j = 0; j < 4; j++) {
        As2[0][akp[j]][arow[j]]     = make_uint2(aR[j].x, aR[j].y);
        As2[0][akp[j] + 1][arow[j]] = make_uint2(aR[j].z, aR[j].w);
    }
    #pragma unroll
    for (int j = 0; j < 3; j++)
        *(uint4*)&Bs2[0][bkp[j]][bn2[j]] = bR[j];
    __syncthreads();

    const int T = K >> 5;   // 3
    for (int t = 0; t < T; t++) {
        const int s = t & 1;
        if (t + 1 < T) {
            const int kt = 16 * (t + 1);
            #pragma unroll
            for (int j = 0; j < 4; j++) aR[j] = *(const uint4*)(aPtr[j] + kt);
            #pragma unroll
            for (int j = 0; j < 3; j++) bR[j] = *(const uint4*)(bPtr[j] + (size_t)kt * N);
        }

        #pragma unroll
        for (int ks = 0; ks < 2; ks++) {
            const int kb = ks * 8;
            uint2 af[2][4];
            #pragma unroll
            for (int mt = 0; mt < 2; mt++) {
                const int m = wm + mt * 16 + gid;
                af[mt][0] = As2[s][kb + tig    ][m];
                af[mt][1] = As2[s][kb + tig    ][m + 8];
                af[mt][2] = As2[s][kb + tig + 4][m];
                af[mt][3] = As2[s][kb + tig + 4][m + 8];
            }
            uint2 bf[6][2];
            #pragma unroll
            for (int nt = 0; nt < 6; nt++) {
                const int n = wn + nt * 8 + gid;
                bf[nt][0] = Bs2[s][kb + tig    ][n];
                bf[nt][1] = Bs2[s][kb + tig + 4][n];
            }
            #pragma unroll
            for (int mt = 0; mt < 2; mt++)
                #pragma unroll
                for (int nt = 0; nt < 6; nt++) {
                    float* c = acc[mt][nt];
                    mma16(c, af[mt][0].x, af[mt][1].x, af[mt][2].x, af[mt][3].x,
                             bf[nt][0].x, bf[nt][1].x);
                    mma16(c, af[mt][0].x, af[mt][1].x, af[mt][2].x, af[mt][3].x,
                             bf[nt][0].y, bf[nt][1].y);
                    mma16(c, af[mt][0].y, af[mt][1].y, af[mt][2].y, af[mt][3].y,
                             bf[nt][0].x, bf[nt][1].x);
                }
        }

        if (t + 1 < T) {
            const int sn = (t + 1) & 1;
            #pragma unroll
            for (int j = 0; j < 4; j++) {
                As2[sn][akp[j]][arow[j]]     = make_uint2(aR[j].x, aR[j].y);
                As2[sn][akp[j] + 1][arow[j]] = make_uint2(aR[j].z, aR[j].w);
            }
            #pragma unroll
            for (int j = 0; j < 3; j++)
                *(uint4*)&Bs2[sn][bkp[j]][bn2[j]] = bR[j];
        }
        __syncthreads();
    }

    float bb[6][2];
    #pragma unroll
    for (int nt = 0; nt < 6; nt++) {
        int c = wn + nt * 8 + tig * 2;
        bb[nt][0] = bias[c];
        bb[nt][1] = bias[c + 1];
    }

    #pragma unroll
    for (int mt = 0; mt < 2; mt++) {
        #pragma unroll
        for (int half = 0; half < 2; half++) {
            int r = m0 + wm + mt * 16 + gid + half * 8;
            size_t orow = (size_t)map_token(r / NNC, r % NNC);
            float* op = out + orow * N + wn + tig * 2;
            const float* rp = res + orow * N + wn + tig * 2;
            #pragma unroll
            for (int nt = 0; nt < 6; nt++) {
                float v0 = acc[mt][nt][half * 2 + 0] + bb[nt][0] + rp[nt * 8];
                float v1 = acc[mt][nt][half * 2 + 1] + bb[nt][1] + rp[nt * 8 + 1];
                *(float2*)(op + nt * 8) = make_float2(v0, v1);
            }
        }
    }
}

// ---------------- fused MLP with fused LN2 prologue ----------------
#define MLP_ASF  (48 * 68)
#define MLP_BS   (48 * 100)
#define MLP_HS   (48 * 68)
#define MLP_SMEM ((MLP_ASF + MLP_BS + MLP_HS) * 8)   // 90624 bytes

__global__ __launch_bounds__(256, 2)
void fused_mlp_kernel(const float* __restrict__ y,     // residual stream (LN2 input + res)
                      const float* __restrict__ lng, const float* __restrict__ lnb,
                      const uint2* __restrict__ W1,
                      const float* __restrict__ b1,
                      const uint2* __restrict__ W2,
                      const float* __restrict__ b2,
                      float* __restrict__ out) {
    extern __shared__ uint2 smemu[];
    uint2 (*AsF)[68]  = reinterpret_cast<uint2(*)[68]>(smemu);
    uint2 (*Bs)[100]  = reinterpret_cast<uint2(*)[100]>(smemu + MLP_ASF);
    uint2 (*Hs)[68]   = reinterpret_cast<uint2(*)[68]>(smemu + MLP_ASF + MLP_BS);
    float* ytmp = (float*)(smemu + MLP_ASF + MLP_BS);   // aliases Hs (25 KB <= 26.1 KB)

    const int tid  = threadIdx.x;
    const int wid  = tid >> 5, lane = tid & 31;
    const int gid  = lane >> 2, tig = lane & 3;
    const int wm   = (wid >> 2) * 32;
    const int wn   = (wid & 3) * 24;
    const int m0   = blockIdx.x * 64;

    // ---- prologue: stage y rows, LN2, write split pairs into AsF ----
    #pragma unroll
    for (int j = 0; j < 12; j++) {
        int c   = tid + 256 * j;
        int row = c / 48, cp = c % 48;
        float2 v = *(const float2*)(y + (size_t)(m0 + row) * DIMC + 2 * cp);
        *(float2*)&ytmp[row * 98 + 2 * cp] = v;
    }
    __syncthreads();
    ln_tile_to_asf(ytmp, AsF, lng, lnb, wid, lane);

    float acc2[2][3][4];
    #pragma unroll
    for (int i = 0; i < 2; i++)
        #pragma unroll
        for (int j = 0; j < 3; j++)
            #pragma unroll
            for (int r = 0; r < 4; r++) acc2[i][j][r] = 0.f;

    for (int cc = 0; cc < 4; cc++) {
        __syncthreads();   // LN done / previous Bs,Hs reads done

        #pragma unroll
        for (int j = 0; j < 9; j++) {
            int c2 = tid + 256 * j;
            int kp = c2 / 48;
            int n2 = (c2 % 48) * 2;
            uint4 v = *(const uint4*)(W1 + (size_t)kp * 384 + cc * 96 + n2);
            *(uint4*)&Bs[kp][n2] = v;
        }
        __syncthreads();

        float acc1[2][3][4];
        #pragma unroll
        for (int i = 0; i < 2; i++)
            #pragma unroll
            for (int j = 0; j < 3; j++)
                #pragma unroll
                for (int r = 0; r < 4; r++) acc1[i][j][r] = 0.f;

        #pragma unroll
        for (int kt = 0; kt < 6; kt++) {
            const int kb = kt * 8;
            uint2 af[2][4];
            #pragma unroll
            for (int mt = 0; mt < 2; mt++) {
                const int m = wm + mt * 16 + gid;
                af[mt][0] = AsF[kb + tig    ][m];
                af[mt][1] = AsF[kb + tig    ][m + 8];
                af[mt][2] = AsF[kb + tig + 4][m];
                af[mt][3] = AsF[kb + tig + 4][m + 8];
            }
            uint2 bf[3][2];
            #pragma unroll
            for (int nt = 0; nt < 3; nt++) {
                const int n = wn + nt * 8 + gid;
                bf[nt][0] = Bs[kb + tig    ][n];
                bf[nt][1] = Bs[kb + tig + 4][n];
            }
            #pragma unroll
            for (int mt = 0; mt < 2; mt++)
                #pragma unroll
                for (int nt = 0; nt < 3; nt++) {
                    float* c = acc1[mt][nt];
                    mma16(c, af[mt][0].x, af[mt][1].x, af[mt][2].x, af[mt][3].x,
                             bf[nt][0].x, bf[nt][1].x);
                    mma16(c, af[mt][0].x, af[mt][1].x, af[mt][2].x, af[mt][3].x,
                             bf[nt][0].y, bf[nt][1].y);
                    mma16(c, af[mt][0].y, af[mt][1].y, af[mt][2].y, af[mt][3].y,
                             bf[nt][0].x, bf[nt][1].x);
                }
        }

        float bb1[3][2];
        #pragma unroll
        for (int nt = 0; nt < 3; nt++) {
            int c = cc * 96 + wn + nt * 8 + tig * 2;
            bb1[nt][0] = b1[c];
            bb1[nt][1] = b1[c + 1];
        }
        #pragma unroll
        for (int mt = 0; mt < 2; mt++) {
            #pragma unroll
            for (int half = 0; half < 2; half++) {
                int r = wm + mt * 16 + gid + half * 8;
                #pragma unroll
                for (int nt = 0; nt < 3; nt++) {
                    float v0 = acc1[mt][nt][half * 2 + 0] + bb1[nt][0];
                    float v1 = acc1[mt][nt][half * 2 + 1] + bb1[nt][1];
                    v0 = 0.5f * v0 * (1.0f + erff(v0 * 0.70710678118654752f));
                    v1 = 0.5f * v1 * (1.0f + erff(v1 * 0.70710678118654752f));
                    int p = (wn >> 1) + nt * 4 + tig;
                    Hs[p][r] = split_bf16_pair(v0, v1);
                }
            }
        }
        __syncthreads();

        #pragma unroll
        for (int j = 0; j < 9; j++) {
            int c2 = tid + 256 * j;
            int kp = c2 / 48;
            int n2 = (c2 % 48) * 2;
            uint4 v = *(const uint4*)(W2 + (size_t)(cc * 48 + kp) * 96 + n2);
            *(uint4*)&Bs[kp][n2] = v;
        }
        __syncthreads();

        #pragma unroll
        for (int kt = 0; kt < 6; kt++) {
            const int kb = kt * 8;
            uint2 af[2][4];
            #pragma unroll
            for (int mt = 0; mt < 2; mt++) {
                const int m = wm + mt * 16 + gid;
                af[mt][0] = Hs[kb + tig    ][m];
                af[mt][1] = Hs[kb + tig    ][m + 8];
                af[mt][2] = Hs[kb + tig + 4][m];
                af[mt][3] = Hs[kb + tig + 4][m + 8];
            }
            uint2 bf[3][2];
            #pragma unroll
            for (int nt = 0; nt < 3; nt++) {
                const int n = wn + nt * 8 + gid;
                bf[nt][0] = Bs[kb + tig    ][n];
                bf[nt][1] = Bs[kb + tig + 4][n];
            }
            #pragma unroll
            for (int mt = 0; mt < 2; mt++)
                #pragma unroll
                for (int nt = 0; nt < 3; nt++) {
                    float* c = acc2[mt][nt];
                    mma16(c, af[mt][0].x, af[mt][1].x, af[mt][2].x, af[mt][3].x,
                             bf[nt][0].x, bf[nt][1].x);
                    mma16(c, af[mt][0].x, af[mt][1].x, af[mt][2].x, af[mt][3].x,
                             bf[nt][0].y, bf[nt][1].y);
                    mma16(c, af[mt][0].y, af[mt][1].y, af[mt][2].y, af[mt][3].y,
                             bf[nt][0].x, bf[nt][1].x);
                }
        }
    }

    float bb2[3][2];
    #pragma unroll
    for (int nt = 0; nt < 3; nt++) {
        int c = wn + nt * 8 + tig * 2;
        bb2[nt][0] = b2[c];
        bb2[nt][1] = b2[c + 1];
    }
    #pragma unroll
    for (int mt = 0; mt < 2; mt++) {
        #pragma unroll
        for (int half = 0; half < 2; half++) {
            size_t rg = (size_t)(m0 + wm + mt * 16 + gid + half * 8);
            float*       op = out + rg * 96 + wn + tig * 2;
            const float* rp = y   + rg * 96 + wn + tig * 2;
            #pragma unroll
            for (int nt = 0; nt < 3; nt++) {
                float v0 = acc2[mt][nt][half * 2 + 0] + bb2[nt][0] + rp[nt * 8];
                float v1 = acc2[mt][nt][half * 2 + 1] + bb2[nt][1] + rp[nt * 8 + 1];
                *(float2*)(op + nt * 8) = make_float2(v0, v1);
            }
        }
    }
}

// ---------------- windowed attention: single-pass streaming softmax (unchanged) ----------------
__global__ __launch_bounds__(64, 8)
void attn_kernel(const float* __restrict__ qkv, const float* __restrict__ rpb) {
    __shared__ float ks[NNC * HEADC];
    __shared__ float vs[NNC * HEADC];
    __shared__ float bt[169];
    __shared__ unsigned char fidx_s[49];
    __shared__ int regn_s[NNC];

    const int bw   = blockIdx.x;
    const int head = blockIdx.y;
    const int base = bw * NNC;
    const int tid  = threadIdx.x;

    for (int idx = tid; idx < NNC * HEADC; idx += 64) {
        int m = idx >> 5, d = idx & 31;
        const float* p = qkv + (size_t)(base + m) * (3 * DIMC) + head * HEADC + d;
        ks[idx] = p[DIMC];
        vs[idx] = p[2 * DIMC];
    }
    for (int i = tid; i < 169; i += 64) bt[i] = rpb[i * NHC + head];
    if (tid < 49) fidx_s[tid] = (unsigned char)((tid / 7) * 13 + (tid % 7));
    if (tid < NNC) {
        int i = tid;
        if (i < PC) regn_s[i] = -1;
        else {
            int p = i - PC;
            int r = p / 7, c = p % 7;
            int w = bw & 63;
            int gh = (w >> 3) * 7 + r;
            int gw = (w & 7) * 7 + c;
            int rh = gh < 49 ? 0 : (gh < 53 ? 1 : 2);
            int rw = gw < 49 ? 0 : (gw < 53 ? 1 : 2);
            regn_s[i] = rh * 3 + rw;
        }
    }
    __syncthreads();

    const int t = tid;
    if (t >= NNC) return;

    const ulonglong2* qp2 = (const ulonglong2*)(qkv + (size_t)(base + t) * (3 * DIMC) + head * HEADC);
    const unsigned long long sc2 = pack2(SCALEC, SCALEC);
    unsigned long long q2[16];
    #pragma unroll
    for (int j = 0; j < 8; j++) {
        ulonglong2 qq = qp2[j];
        q2[2 * j]     = mul2(qq.x, sc2);
        q2[2 * j + 1] = mul2(qq.y, sc2);
    }

    const bool feat = (t >= PC);
    int tb = 0;
    unsigned mlo = 0, mhi = 0;
    if (feat) {
        int p = t - PC;
        tb = (p / 7 + 6) * 13 + (p % 7 + 6);
        int myreg = regn_s[t];
        #pragma unroll 7
        for (int m = PC; m < NNC; m++) {
            if (regn_s[m] != myreg) {
                if (m < 32) mlo |= 1u << m;
                else        mhi |= 1u << (m - 32);
            }
        }
    }

    unsigned long long acc2[16];
    #pragma unroll
    for (int j = 0; j < 16; j++) acc2[j] = 0ull;
    float sum = 0.f;

    #pragma unroll 3
    for (int m = 0; m < NNC; m++) {
        const ulonglong2* k2p = (const ulonglong2*)(ks + m * HEADC);
        unsigned long long c0 = 0ull, c1 = 0ull, c2 = 0ull, c3 = 0ull;
        #pragma unroll
        for (int j = 0; j < 8; j += 2) {
            ulonglong2 ka = k2p[j];
            ulonglong2 kb = k2p[j + 1];
            c0 = fma2(q2[2 * j],     ka.x, c0);
            c1 = fma2(q2[2 * j + 1], ka.y, c1);
            c2 = fma2(q2[2 * j + 2], kb.x, c2);
            c3 = fma2(q2[2 * j + 3], kb.y, c3);
        }
        unsigned long long cs = add2(add2(c0, c1), add2(c2, c3));
        float alo, ahi;
        unpack2(alo, ahi, cs);
        float a = alo + ahi;
        if (feat && m >= PC) {
            int idx = tb - (int)fidx_s[m - PC];
            float badd = bt[idx];
            bool msk = (m < 32) ? ((mlo >> m) & 1u) : ((mhi >> (m - 32)) & 1u);
            a += msk ? (badd - 100.f) : badd;
        }
        const float e = __expf(a);
        sum += e;
        const unsigned long long e2 = pack2(e, e);
        const ulonglong2* v2p = (const ulonglong2*)(vs + m * HEADC);
        #pragma unroll
        for (int j = 0; j < 8; j++) {
            ulonglong2 vv = v2p[j];
            acc2[2 * j]     = fma2(e2, vv.x, acc2[2 * j]);
            acc2[2 * j + 1] = fma2(e2, vv.y, acc2[2 * j + 1]);
        }
    }

    const float inv = 1.0f / sum;
    const unsigned long long inv2 = pack2(inv, inv);

    uint2* op = g_attno_sp + (size_t)(base + t) * 48 + head * 16;
    #pragma unroll
    for (int j = 0; j < 16; j++) {
        unsigned long long r = mul2(acc2[j], inv2);
        float lo, hi;
        unpack2(lo, hi, r);
        op[j] = split_bf16_pair(lo, hi);
    }
}

// ---------------- launch ----------------
extern "C" void kernel_launch(void* const* d_in, const int* in_sizes, int n_in,
                              void* d_out, int out_size) {
    const float* x       = (const float*)d_in[0];
    const float* norm1_g = (const float*)d_in[1];
    const float* norm1_b = (const float*)d_in[2];
    const float* qkv_w   = (const float*)d_in[3];
    const float* qkv_b   = (const float*)d_in[4];
    const float* rpb     = (const float*)d_in[5];
    const float* proj_w  = (const float*)d_in[6];
    const float* proj_b  = (const float*)d_in[7];
    const float* norm2_g = (const float*)d_in[8];
    const float* norm2_b = (const float*)d_in[9];
    const float* fc1_w   = (const float*)d_in[10];
    const float* fc1_b   = (const float*)d_in[11];
    const float* fc2_w   = (const float*)d_in[12];
    const float* fc2_b   = (const float*)d_in[13];
    float* out = (float*)d_out;

    uint2 *p_attno, *p_wq, *p_wp, *p_w1, *p_w2;
    float *p_qkv, *p_y;
    cudaGetSymbolAddress((void**)&p_qkv,   g_qkv);
    cudaGetSymbolAddress((void**)&p_attno, g_attno_sp);
    cudaGetSymbolAddress((void**)&p_y,     g_y);
    cudaGetSymbolAddress((void**)&p_wq,    g_wq_sp);
    cudaGetSymbolAddress((void**)&p_wp,    g_wp_sp);
    cudaGetSymbolAddress((void**)&p_w1,    g_w1_sp);
    cudaGetSymbolAddress((void**)&p_w2,    g_w2_sp);

    cudaFuncSetAttribute(qkv_kernel, cudaFuncAttributeMaxDynamicSharedMemorySize, QKV_SMEM);
    cudaFuncSetAttribute(proj_gemm,  cudaFuncAttributeMaxDynamicSharedMemorySize, GEMM_SMEM);
    cudaFuncSetAttribute(fused_mlp_kernel, cudaFuncAttributeMaxDynamicSharedMemorySize, MLP_SMEM);

    // 0. pre-split weights
    split_w_kernel<<<216, 256>>>(qkv_w, proj_w, fc1_w, fc2_w);
    // 1+2. QKV GEMM with fused LN1 + window gather -> float
    qkv_kernel<<<MROWS / 64, 256, QKV_SMEM>>>(x, norm1_g, norm1_b, p_wq, qkv_b, p_qkv);
    // 3. windowed attention, single-pass streaming softmax (split out)
    attn_kernel<<<dim3(BATCHC * NWC, NHC), 64>>>(p_qkv, rpb);
    // 4. proj GEMM + scatter + residual-1 -> g_y
    proj_gemm<<<dim3(1, MROWS / 128), 256, GEMM_SMEM>>>(p_attno, p_wp, proj_b, x, p_y);
    // 5+6+7. fused MLP with fused LN2: out = y + GELU(LN(y) @ W1 + b1) @ W2 + b2
    fused_mlp_kernel<<<MROWS / 64, 256, MLP_SMEM>>>(p_y, norm2_g, norm2_b,
                                                    p_w1, fc1_b, p_w2, fc2_b, out);
}

// round 15
// speedup vs baseline: 1.0396x; 1.0396x over previous
#include <cuda_runtime.h>
#include <cuda_bf16.h>
#include <math.h>

// ---------------- problem constants ----------------
#define DIMC    96
#define NHC     3
#define HEADC   32
#define WSC     7
#define SHIFTC  3
#define PC      5
#define HC      56
#define NWC     64
#define TPC     320
#define NNC     54
#define BATCHC  64
#define TOKC    3456
#define MROWS   (BATCHC * NWC * NNC)   // 221184
#define HIDC    384
#define SCALEC  0.17677669529663687f

// ---------------- scratch ----------------
__device__ float               g_qkv     [(size_t)MROWS * 3 * DIMC];
__device__ __align__(16) uint2 g_attno_sp[MROWS * 48];            // attn out, window order
__device__ float               g_y       [MROWS * DIMC];          // residual stream (fp32)
// pre-split weights [kpair][n]
__device__ __align__(16) uint2 g_wq_sp[48 * 288];
__device__ __align__(16) uint2 g_wp_sp[48 * 96];
__device__ __align__(16) uint2 g_w1_sp[48 * 384];
__device__ __align__(16) uint2 g_w2_sp[192 * 96];

__device__ __forceinline__ int map_token(int bw, int n) {
    int b = bw >> 6;
    int w = bw & 63;
    int tok;
    if (n < PC) {
        tok = w * PC + n;
    } else {
        int p  = n - PC;
        int r  = p / 7, c = p % 7;
        int wh = w >> 3, ww = w & 7;
        int hr = wh * 7 + r + SHIFTC; if (hr >= HC) hr -= HC;
        int wc = ww * 7 + c + SHIFTC; if (wc >= HC) wc -= HC;
        tok = TPC + hr * HC + wc;
    }
    return b * TOKC + tok;
}

__device__ __forceinline__ float warp_sum(float v) {
    #pragma unroll
    for (int o = 16; o; o >>= 1) v += __shfl_xor_sync(0xffffffffu, v, o);
    return v;
}

__device__ __forceinline__ uint2 split_bf16_pair(float x0, float x1) {
    __nv_bfloat16 h0 = __float2bfloat16(x0);
    __nv_bfloat16 h1 = __float2bfloat16(x1);
    float r0 = x0 - __bfloat162float(h0);
    float r1 = x1 - __bfloat162float(h1);
    __nv_bfloat16 l0 = __float2bfloat16(r0);
    __nv_bfloat16 l1 = __float2bfloat16(r1);
    uint2 o;
    o.x = ((unsigned)__bfloat16_as_ushort(h1) << 16) | (unsigned)__bfloat16_as_ushort(h0);
    o.y = ((unsigned)__bfloat16_as_ushort(l1) << 16) | (unsigned)__bfloat16_as_ushort(l0);
    return o;
}

// ---- packed f32x2 helpers ----
__device__ __forceinline__ unsigned long long pack2(float lo, float hi) {
    unsigned long long d;
    asm("mov.b64 %0, {%1, %2};" : "=l"(d) : "f"(lo), "f"(hi));
    return d;
}
__device__ __forceinline__ void unpack2(float& lo, float& hi, unsigned long long v) {
    asm("mov.b64 {%0, %1}, %2;" : "=f"(lo), "=f"(hi) : "l"(v));
}
__device__ __forceinline__ unsigned long long fma2(unsigned long long a, unsigned long long b,
                                                   unsigned long long c) {
    unsigned long long d;
    asm("fma.rn.f32x2 %0, %1, %2, %3;" : "=l"(d) : "l"(a), "l"(b), "l"(c));
    return d;
}
__device__ __forceinline__ unsigned long long add2(unsigned long long a, unsigned long long b) {
    unsigned long long d;
    asm("add.rn.f32x2 %0, %1, %2;" : "=l"(d) : "l"(a), "l"(b));
    return d;
}
__device__ __forceinline__ unsigned long long mul2(unsigned long long a, unsigned long long b) {
    unsigned long long d;
    asm("mul.rn.f32x2 %0, %1, %2;" : "=l"(d) : "l"(a), "l"(b));
    return d;
}

// ---------------- weight pre-split ----------------
__global__ __launch_bounds__(256)
void split_w_kernel(const float* __restrict__ qkv_w, const float* __restrict__ proj_w,
                    const float* __restrict__ fc1_w, const float* __restrict__ fc2_w) {
    int i = blockIdx.x * blockDim.x + threadIdx.x;
    if (i < 13824) {
        int kp = i / 288, n = i % 288;
        g_wq_sp[i] = split_bf16_pair(qkv_w[(2 * kp) * 288 + n], qkv_w[(2 * kp + 1) * 288 + n]);
    } else if (i < 18432) {
        int j = i - 13824, kp = j / 96, n = j % 96;
        g_wp_sp[j] = split_bf16_pair(proj_w[(2 * kp) * 96 + n], proj_w[(2 * kp + 1) * 96 + n]);
    } else if (i < 36864) {
        int j = i - 18432, kp = j / 384, n = j % 384;
        g_w1_sp[j] = split_bf16_pair(fc1_w[(2 * kp) * 384 + n], fc1_w[(2 * kp + 1) * 384 + n]);
    } else if (i < 55296) {
        int j = i - 36864, kp = j / 96, n = j % 96;
        g_w2_sp[j] = split_bf16_pair(fc2_w[(2 * kp) * 96 + n], fc2_w[(2 * kp + 1) * 96 + n]);
    }
}

// ---------------- BF16x3 MMA primitive ----------------
__device__ __forceinline__ void mma16(float c[4],
                                      unsigned a0, unsigned a1, unsigned a2, unsigned a3,
                                      unsigned b0, unsigned b1) {
    asm volatile("mma.sync.aligned.m16n8k16.row.col.f32.bf16.bf16.f32 "
                 "{%0,%1,%2,%3}, {%4,%5,%6,%7}, {%8,%9}, {%0,%1,%2,%3};\n"
                 : "+f"(c[0]), "+f"(c[1]), "+f"(c[2]), "+f"(c[3])
                 : "r"(a0), "r"(a1), "r"(a2), "r"(a3), "r"(b0), "r"(b1));
}

// LN a 64-row fp32 smem tile [64][100] into split pairs AsF[kpair][row]. 8 warps x 8 rows.
__device__ __forceinline__ void ln_tile_to_asf(const float* ytmp, uint2 (*AsF)[68],
                                               const float* __restrict__ lng,
                                               const float* __restrict__ lnb,
                                               int wid, int lane) {
    const float2* g2 = (const float2*)lng;
    const float2* b2 = (const float2*)lnb;
    float2 G0 = g2[lane], B0 = b2[lane];
    float2 G1 = make_float2(0.f, 0.f), B1 = make_float2(0.f, 0.f);
    if (lane < 16) { G1 = g2[32 + lane]; B1 = b2[32 + lane]; }
    #pragma unroll
    for (int rr = 0; rr < 8; rr++) {
        int r = wid * 8 + rr;
        float2 a0 = *(const float2*)&ytmp[r * 100 + 2 * lane];
        float2 a1 = make_float2(0.f, 0.f);
        if (lane < 16) a1 = *(const float2*)&ytmp[r * 100 + 64 + 2 * lane];
        float s = a0.x + a0.y + a1.x + a1.y;
        float mean = warp_sum(s) * (1.f / 96.f);
        float d0x = a0.x - mean, d0y = a0.y - mean;
        float d1x = a1.x - mean, d1y = a1.y - mean;
        float vq = d0x * d0x + d0y * d0y + (lane < 16 ? d1x * d1x + d1y * d1y : 0.f);
        float var = warp_sum(vq) * (1.f / 96.f);
        float inv = rsqrtf(var + 1e-5f);
        AsF[lane][r] = split_bf16_pair(d0x * inv * G0.x + B0.x, d0y * inv * G0.y + B0.y);
        if (lane < 16)
            AsF[32 + lane][r] = split_bf16_pair(d1x * inv * G1.x + B1.x, d1y * inv * G1.y + B1.y);
    }
}

// ---------------- QKV GEMM with fused LN1 + shifted-window gather ----------------
#define QKV_ASF  (48 * 68)
#define QKV_BS   (48 * 100)
#define QKV_SMEM ((QKV_ASF + QKV_BS) * 8)   // 64512 bytes

__global__ __launch_bounds__(256, 2)
void qkv_kernel(const float* __restrict__ x,
                const float* __restrict__ lng, const float* __restrict__ lnb,
                const uint2* __restrict__ W,
                const float* __restrict__ bias,
                float* __restrict__ out) {
    extern __shared__ uint2 smemu[];
    uint2 (*AsF)[68] = reinterpret_cast<uint2(*)[68]>(smemu);
    uint2 (*Bs)[100] = reinterpret_cast<uint2(*)[100]>(smemu + QKV_ASF);
    float* ytmp = (float*)(smemu + QKV_ASF);   // aliases Bs region (25.6 KB <= 38.4 KB)
    __shared__ int toks[64];

    const int tid  = threadIdx.x;
    const int wid  = tid >> 5, lane = tid & 31;
    const int gid  = lane >> 2, tig = lane & 3;
    const int wm   = (wid >> 2) * 32;
    const int wn   = (wid & 3) * 24;
    const int m0   = blockIdx.x * 64;

    // ---- prologue: gather x rows (float4), LN1, write split pairs into AsF ----
    if (tid < 64) {
        int r = m0 + tid;
        toks[tid] = map_token(r / NNC, r % NNC);
    }
    __syncthreads();
    #pragma unroll
    for (int j = 0; j < 6; j++) {                  // 64 rows x 24 float4
        int c   = tid + 256 * j;
        int row = c / 24, q4 = c % 24;
        float4 v = *((const float4*)(x + (size_t)toks[row] * DIMC) + q4);
        *(float4*)&ytmp[row * 100 + q4 * 4] = v;
    }
    __syncthreads();
    ln_tile_to_asf(ytmp, AsF, lng, lnb, wid, lane);

    for (int cc = 0; cc < 3; cc++) {
        __syncthreads();   // LN done for all warps (cc=0) / Bs reads done (cc>0)

        #pragma unroll
        for (int j = 0; j < 9; j++) {
            int c2 = tid + 256 * j;
            int kp = c2 / 48;
            int n2 = (c2 % 48) * 2;
            uint4 v = *(const uint4*)(W + (size_t)kp * 288 + cc * 96 + n2);
            *(uint4*)&Bs[kp][n2] = v;
        }
        __syncthreads();

        float acc[2][3][4];
        #pragma unroll
        for (int i = 0; i < 2; i++)
            #pragma unroll
            for (int j = 0; j < 3; j++)
                #pragma unroll
                for (int r = 0; r < 4; r++) acc[i][j][r] = 0.f;

        #pragma unroll
        for (int kt = 0; kt < 6; kt++) {
            const int kb = kt * 8;
            uint2 af[2][4];
            #pragma unroll
            for (int mt = 0; mt < 2; mt++) {
                const int m = wm + mt * 16 + gid;
                af[mt][0] = AsF[kb + tig    ][m];
                af[mt][1] = AsF[kb + tig    ][m + 8];
                af[mt][2] = AsF[kb + tig + 4][m];
                af[mt][3] = AsF[kb + tig + 4][m + 8];
            }
            uint2 bf[3][2];
            #pragma unroll
            for (int nt = 0; nt < 3; nt++) {
                const int n = wn + nt * 8 + gid;
                bf[nt][0] = Bs[kb + tig    ][n];
                bf[nt][1] = Bs[kb + tig + 4][n];
            }
            #pragma unroll
            for (int mt = 0; mt < 2; mt++)
                #pragma unroll
                for (int nt = 0; nt < 3; nt++) {
                    float* c = acc[mt][nt];
                    mma16(c, af[mt][0].x, af[mt][1].x, af[mt][2].x, af[mt][3].x,
                             bf[nt][0].x, bf[nt][1].x);
                    mma16(c, af[mt][0].x, af[mt][1].x, af[mt][2].x, af[mt][3].x,
                             bf[nt][0].y, bf[nt][1].y);
                    mma16(c, af[mt][0].y, af[mt][1].y, af[mt][2].y, af[mt][3].y,
                             bf[nt][0].x, bf[nt][1].x);
                }
        }

        float bb[3][2];
        #pragma unroll
        for (int nt = 0; nt < 3; nt++) {
            int c = cc * 96 + wn + nt * 8 + tig * 2;
            bb[nt][0] = bias[c];
            bb[nt][1] = bias[c + 1];
        }
        #pragma unroll
        for (int mt = 0; mt < 2; mt++) {
            #pragma unroll
            for (int half = 0; half < 2; half++) {
                size_t rg = (size_t)(m0 + wm + mt * 16 + gid + half * 8);
                float* op = out + rg * 288 + cc * 96 + wn + tig * 2;
                #pragma unroll
                for (int nt = 0; nt < 3; nt++) {
                    float v0 = acc[mt][nt][half * 2 + 0] + bb[nt][0];
                    float v1 = acc[mt][nt][half * 2 + 1] + bb[nt][1];
                    *(float2*)(op + nt * 8) = make_float2(v0, v1);
                }
            }
        }
    }
}

// ---------------- proj GEMM (unchanged) ----------------
#define GEMM_SMEM ((2 * 16 * 132 + 2 * 16 * 100) * 8)   // 59392 bytes

__global__ __launch_bounds__(256, 2)
void proj_gemm(const uint2* __restrict__ A, const uint2* __restrict__ Bw,
               const float* __restrict__ bias, const float* __restrict__ res,
               float* __restrict__ out) {
    const int N = 96, K = 96, KP = 48;
    extern __shared__ uint2 smemu[];
    uint2 (*As2)[16][132] = reinterpret_cast<uint2(*)[16][132]>(smemu);
    uint2 (*Bs2)[16][100] = reinterpret_cast<uint2(*)[16][100]>(smemu + 2 * 16 * 132);

    const int tid  = threadIdx.x;
    const int wid  = tid >> 5, lane = tid & 31;
    const int gid  = lane >> 2, tig = lane & 3;
    const int wm   = (wid >> 1) * 32;
    const int wn   = (wid & 1) * 48;
    const int m0   = blockIdx.y * 128;

    int arow[4], akp[4];
    const uint2* aPtr[4];
    #pragma unroll
    for (int j = 0; j < 4; j++) {
        int c = tid + 256 * j;
        arow[j] = c >> 3;
        akp[j]  = (c & 7) * 2;
        aPtr[j] = A + (size_t)(m0 + arow[j]) * KP + akp[j];
    }
    int bkp[3], bn2[3];
    const uint2* bPtr[3];
    #pragma unroll
    for (int j = 0; j < 3; j++) {
        int c = tid + 256 * j;
        bkp[j] = c / 48;
        bn2[j] = (c % 48) * 2;
        bPtr[j] = Bw + (size_t)bkp[j] * N + bn2[j];
    }

    float acc[2][6][4];
    #pragma unroll
    for (int i = 0; i < 2; i++)
        #pragma unroll
        for (int j = 0; j < 6; j++)
            #pragma unroll
            for (int r = 0; r < 4; r++) acc[i][j][r] = 0.f;

    uint4 aR[4], bR[3];
    #pragma unroll
    for (int j = 0; j < 4; j++) aR[j] = *(const uint4*)(aPtr[j]);
    #pragma unroll
    for (int j = 0; j < 3; j++) bR[j] = *(const uint4*)(bPtr[j]);

    #pragma unroll
    for (int j = 0; j < 4; j++) {
        As2[0][akp[j]][arow[j]]     = make_uint2(aR[j].x, aR[j].y);
        As2[0][akp[j] + 1][arow[j]] = make_uint2(aR[j].z, aR[j].w);
    }
    #pragma unroll
    for (int j = 0; j < 3; j++)
        *(uint4*)&Bs2[0][bkp[j]][bn2[j]] = bR[j];
    __syncthreads();

    const int T = K >> 5;   // 3
    for (int t = 0; t < T; t++) {
        const int s = t & 1;
        if (t + 1 < T) {
            const int kt = 16 * (t + 1);
            #pragma unroll
            for (int j = 0; j < 4; j++) aR[j] = *(const uint4*)(aPtr[j] + kt);
            #pragma unroll
            for (int j = 0; j < 3; j++) bR[j] = *(const uint4*)(bPtr[j] + (size_t)kt * N);
        }

        #pragma unroll
        for (int ks = 0; ks < 2; ks++) {
            const int kb = ks * 8;
            uint2 af[2][4];
            #pragma unroll
            for (int mt = 0; mt < 2; mt++) {
                const int m = wm + mt * 16 + gid;
                af[mt][0] = As2[s][kb + tig    ][m];
                af[mt][1] = As2[s][kb + tig    ][m + 8];
                af[mt][2] = As2[s][kb + tig + 4][m];
                af[mt][3] = As2[s][kb + tig + 4][m + 8];
            }
            uint2 bf[6][2];
            #pragma unroll
            for (int nt = 0; nt < 6; nt++) {
                const int n = wn + nt * 8 + gid;
                bf[nt][0] = Bs2[s][kb + tig    ][n];
                bf[nt][1] = Bs2[s][kb + tig + 4][n];
            }
            #pragma unroll
            for (int mt = 0; mt < 2; mt++)
                #pragma unroll
                for (int nt = 0; nt < 6; nt++) {
                    float* c = acc[mt][nt];
                    mma16(c, af[mt][0].x, af[mt][1].x, af[mt][2].x, af[mt][3].x,
                             bf[nt][0].x, bf[nt][1].x);
                    mma16(c, af[mt][0].x, af[mt][1].x, af[mt][2].x, af[mt][3].x,
                             bf[nt][0].y, bf[nt][1].y);
                    mma16(c, af[mt][0].y, af[mt][1].y, af[mt][2].y, af[mt][3].y,
                             bf[nt][0].x, bf[nt][1].x);
                }
        }

        if (t + 1 < T) {
            const int sn = (t + 1) & 1;
            #pragma unroll
            for (int j = 0; j < 4; j++) {
                As2[sn][akp[j]][arow[j]]     = make_uint2(aR[j].x, aR[j].y);
                As2[sn][akp[j] + 1][arow[j]] = make_uint2(aR[j].z, aR[j].w);
            }
            #pragma unroll
            for (int j = 0; j < 3; j++)
                *(uint4*)&Bs2[sn][bkp[j]][bn2[j]] = bR[j];
        }
        __syncthreads();
    }

    float bb[6][2];
    #pragma unroll
    for (int nt = 0; nt < 6; nt++) {
        int c = wn + nt * 8 + tig * 2;
        bb[nt][0] = bias[c];
        bb[nt][1] = bias[c + 1];
    }

    #pragma unroll
    for (int mt = 0; mt < 2; mt++) {
        #pragma unroll
        for (int half = 0; half < 2; half++) {
            int r = m0 + wm + mt * 16 + gid + half * 8;
            size_t orow = (size_t)map_token(r / NNC, r % NNC);
            float* op = out + orow * N + wn + tig * 2;
            const float* rp = res + orow * N + wn + tig * 2;
            #pragma unroll
            for (int nt = 0; nt < 6; nt++) {
                float v0 = acc[mt][nt][half * 2 + 0] + bb[nt][0] + rp[nt * 8];
                float v1 = acc[mt][nt][half * 2 + 1] + bb[nt][1] + rp[nt * 8 + 1];
                *(float2*)(op + nt * 8) = make_float2(v0, v1);
            }
        }
    }
}

// ---------------- fused MLP: LN2 prologue + residual-from-smem acc init ----------------
#define MLP_ASF  (48 * 68)
#define MLP_BS   (48 * 100)
#define MLP_HS   (48 * 68)
#define MLP_SMEM ((MLP_ASF + MLP_BS + MLP_HS) * 8)   // 90624 bytes

__global__ __launch_bounds__(256, 2)
void fused_mlp_kernel(const float* __restrict__ y,     // residual stream (LN2 input + res)
                      const float* __restrict__ lng, const float* __restrict__ lnb,
                      const uint2* __restrict__ W1,
                      const float* __restrict__ b1,
                      const uint2* __restrict__ W2,
                      const float* __restrict__ b2,
                      float* __restrict__ out) {
    extern __shared__ uint2 smemu[];
    uint2 (*AsF)[68]  = reinterpret_cast<uint2(*)[68]>(smemu);
    uint2 (*Bs)[100]  = reinterpret_cast<uint2(*)[100]>(smemu + MLP_ASF);
    uint2 (*Hs)[68]   = reinterpret_cast<uint2(*)[68]>(smemu + MLP_ASF + MLP_BS);
    float* ytmp = (float*)(smemu + MLP_ASF + MLP_BS);   // aliases Hs (25.6 KB <= 26.1 KB)

    const int tid  = threadIdx.x;
    const int wid  = tid >> 5, lane = tid & 31;
    const int gid  = lane >> 2, tig = lane & 3;
    const int wm   = (wid >> 2) * 32;
    const int wn   = (wid & 3) * 24;
    const int m0   = blockIdx.x * 64;

    // ---- prologue: stage y rows (float4), LN2, write split pairs into AsF ----
    #pragma unroll
    for (int j = 0; j < 6; j++) {
        int c   = tid + 256 * j;
        int row = c / 24, q4 = c % 24;
        float4 v = *((const float4*)(y + (size_t)(m0 + row) * DIMC) + q4);
        *(float4*)&ytmp[row * 100 + q4 * 4] = v;
    }
    __syncthreads();
    ln_tile_to_asf(ytmp, AsF, lng, lnb, wid, lane);

    // ---- init acc2 from the staged residual (ytmp still intact; Hs writes only
    //      happen after the cc-loop's first barrier, which we reach only after this) ----
    float acc2[2][3][4];
    #pragma unroll
    for (int mt = 0; mt < 2; mt++) {
        #pragma unroll
        for (int half = 0; half < 2; half++) {
            int lr = wm + mt * 16 + gid + half * 8;
            #pragma unroll
            for (int nt = 0; nt < 3; nt++) {
                float2 rv = *(const float2*)&ytmp[lr * 100 + wn + tig * 2 + nt * 8];
                acc2[mt][nt][half * 2 + 0] = rv.x;
                acc2[mt][nt][half * 2 + 1] = rv.y;
            }
        }
    }

    for (int cc = 0; cc < 4; cc++) {
        __syncthreads();   // LN + residual reads done / previous Bs,Hs reads done

        #pragma unroll
        for (int j = 0; j < 9; j++) {
            int c2 = tid + 256 * j;
            int kp = c2 / 48;
            int n2 = (c2 % 48) * 2;
            uint4 v = *(const uint4*)(W1 + (size_t)kp * 384 + cc * 96 + n2);
            *(uint4*)&Bs[kp][n2] = v;
        }
        __syncthreads();

        float acc1[2][3][4];
        #pragma unroll
        for (int i = 0; i < 2; i++)
            #pragma unroll
            for (int j = 0; j < 3; j++)
                #pragma unroll
                for (int r = 0; r < 4; r++) acc1[i][j][r] = 0.f;

        #pragma unroll
        for (int kt = 0; kt < 6; kt++) {
            const int kb = kt * 8;
            uint2 af[2][4];
            #pragma unroll
            for (int mt = 0; mt < 2; mt++) {
                const int m = wm + mt * 16 + gid;
                af[mt][0] = AsF[kb + tig    ][m];
                af[mt][1] = AsF[kb + tig    ][m + 8];
                af[mt][2] = AsF[kb + tig + 4][m];
                af[mt][3] = AsF[kb + tig + 4][m + 8];
            }
            uint2 bf[3][2];
            #pragma unroll
            for (int nt = 0; nt < 3; nt++) {
                const int n = wn + nt * 8 + gid;
                bf[nt][0] = Bs[kb + tig    ][n];
                bf[nt][1] = Bs[kb + tig + 4][n];
            }
            #pragma unroll
            for (int mt = 0; mt < 2; mt++)
                #pragma unroll
                for (int nt = 0; nt < 3; nt++) {
                    float* c = acc1[mt][nt];
                    mma16(c, af[mt][0].x, af[mt][1].x, af[mt][2].x, af[mt][3].x,
                             bf[nt][0].x, bf[nt][1].x);
                    mma16(c, af[mt][0].x, af[mt][1].x, af[mt][2].x, af[mt][3].x,
                             bf[nt][0].y, bf[nt][1].y);
                    mma16(c, af[mt][0].y, af[mt][1].y, af[mt][2].y, af[mt][3].y,
                             bf[nt][0].x, bf[nt][1].x);
                }
        }

        float bb1[3][2];
        #pragma unroll
        for (int nt = 0; nt < 3; nt++) {
            int c = cc * 96 + wn + nt * 8 + tig * 2;
            bb1[nt][0] = b1[c];
            bb1[nt][1] = b1[c + 1];
        }
        #pragma unroll
        for (int mt = 0; mt < 2; mt++) {
            #pragma unroll
            for (int half = 0; half < 2; half++) {
                int r = wm + mt * 16 + gid + half * 8;
                #pragma unroll
                for (int nt = 0; nt < 3; nt++) {
                    float v0 = acc1[mt][nt][half * 2 + 0] + bb1[nt][0];
                    float v1 = acc1[mt][nt][half * 2 + 1] + bb1[nt][1];
                    v0 = 0.5f * v0 * (1.0f + erff(v0 * 0.70710678118654752f));
                    v1 = 0.5f * v1 * (1.0f + erff(v1 * 0.70710678118654752f));
                    int p = (wn >> 1) + nt * 4 + tig;
                    Hs[p][r] = split_bf16_pair(v0, v1);
                }
            }
        }
        __syncthreads();

        #pragma unroll
        for (int j = 0; j < 9; j++) {
            int c2 = tid + 256 * j;
            int kp = c2 / 48;
            int n2 = (c2 % 48) * 2;
            uint4 v = *(const uint4*)(W2 + (size_t)(cc * 48 + kp) * 96 + n2);
            *(uint4*)&Bs[kp][n2] = v;
        }
        __syncthreads();

        #pragma unroll
        for (int kt = 0; kt < 6; kt++) {
            const int kb = kt * 8;
            uint2 af[2][4];
            #pragma unroll
            for (int mt = 0; mt < 2; mt++) {
                const int m = wm + mt * 16 + gid;
                af[mt][0] = Hs[kb + tig    ][m];
                af[mt][1] = Hs[kb + tig    ][m + 8];
                af[mt][2] = Hs[kb + tig + 4][m];
                af[mt][3] = Hs[kb + tig + 4][m + 8];
            }
            uint2 bf[3][2];
            #pragma unroll
            for (int nt = 0; nt < 3; nt++) {
                const int n = wn + nt * 8 + gid;
                bf[nt][0] = Bs[kb + tig    ][n];
                bf[nt][1] = Bs[kb + tig + 4][n];
            }
            #pragma unroll
            for (int mt = 0; mt < 2; mt++)
                #pragma unroll
                for (int nt = 0; nt < 3; nt++) {
                    float* c = acc2[mt][nt];
                    mma16(c, af[mt][0].x, af[mt][1].x, af[mt][2].x, af[mt][3].x,
                             bf[nt][0].x, bf[nt][1].x);
                    mma16(c, af[mt][0].x, af[mt][1].x, af[mt][2].x, af[mt][3].x,
                             bf[nt][0].y, bf[nt][1].y);
                    mma16(c, af[mt][0].y, af[mt][1].y, af[mt][2].y, af[mt][3].y,
                             bf[nt][0].x, bf[nt][1].x);
                }
        }
    }

    // ---- final epilogue: +b2 only (residual already inside acc2) ----
    float bb2[3][2];
    #pragma unroll
    for (int nt = 0; nt < 3; nt++) {
        int c = wn + nt * 8 + tig * 2;
        bb2[nt][0] = b2[c];
        bb2[nt][1] = b2[c + 1];
    }
    #pragma unroll
    for (int mt = 0; mt < 2; mt++) {
        #pragma unroll
        for (int half = 0; half < 2; half++) {
            size_t rg = (size_t)(m0 + wm + mt * 16 + gid + half * 8);
            float* op = out + rg * 96 + wn + tig * 2;
            #pragma unroll
            for (int nt = 0; nt < 3; nt++) {
                float v0 = acc2[mt][nt][half * 2 + 0] + bb2[nt][0];
                float v1 = acc2[mt][nt][half * 2 + 1] + bb2[nt][1];
                *(float2*)(op + nt * 8) = make_float2(v0, v1);
            }
        }
    }
}

// ---------------- windowed attention: single-pass streaming softmax (unchanged) ----------------
__global__ __launch_bounds__(64, 8)
void attn_kernel(const float* __restrict__ qkv, const float* __restrict__ rpb) {
    __shared__ float ks[NNC * HEADC];
    __shared__ float vs[NNC * HEADC];
    __shared__ float bt[169];
    __shared__ unsigned char fidx_s[49];
    __shared__ int regn_s[NNC];

    const int bw   = blockIdx.x;
    const int head = blockIdx.y;
    const int base = bw * NNC;
    const int tid  = threadIdx.x;

    for (int idx = tid; idx < NNC * HEADC; idx += 64) {
        int m = idx >> 5, d = idx & 31;
        const float* p = qkv + (size_t)(base + m) * (3 * DIMC) + head * HEADC + d;
        ks[idx] = p[DIMC];
        vs[idx] = p[2 * DIMC];
    }
    for (int i = tid; i < 169; i += 64) bt[i] = rpb[i * NHC + head];
    if (tid < 49) fidx_s[tid] = (unsigned char)((tid / 7) * 13 + (tid % 7));
    if (tid < NNC) {
        int i = tid;
        if (i < PC) regn_s[i] = -1;
        else {
            int p = i - PC;
            int r = p / 7, c = p % 7;
            int w = bw & 63;
            int gh = (w >> 3) * 7 + r;
            int gw = (w & 7) * 7 + c;
            int rh = gh < 49 ? 0 : (gh < 53 ? 1 : 2);
            int rw = gw < 49 ? 0 : (gw < 53 ? 1 : 2);
            regn_s[i] = rh * 3 + rw;
        }
    }
    __syncthreads();

    const int t = tid;
    if (t >= NNC) return;

    const ulonglong2* qp2 = (const ulonglong2*)(qkv + (size_t)(base + t) * (3 * DIMC) + head * HEADC);
    const unsigned long long sc2 = pack2(SCALEC, SCALEC);
    unsigned long long q2[16];
    #pragma unroll
    for (int j = 0; j < 8; j++) {
        ulonglong2 qq = qp2[j];
        q2[2 * j]     = mul2(qq.x, sc2);
        q2[2 * j + 1] = mul2(qq.y, sc2);
    }

    const bool feat = (t >= PC);
    int tb = 0;
    unsigned mlo = 0, mhi = 0;
    if (feat) {
        int p = t - PC;
        tb = (p / 7 + 6) * 13 + (p % 7 + 6);
        int myreg = regn_s[t];
        #pragma unroll 7
        for (int m = PC; m < NNC; m++) {
            if (regn_s[m] != myreg) {
                if (m < 32) mlo |= 1u << m;
                else        mhi |= 1u << (m - 32);
            }
        }
    }

    unsigned long long acc2[16];
    #pragma unroll
    for (int j = 0; j < 16; j++) acc2[j] = 0ull;
    float sum = 0.f;

    #pragma unroll 3
    for (int m = 0; m < NNC; m++) {
        const ulonglong2* k2p = (const ulonglong2*)(ks + m * HEADC);
        unsigned long long c0 = 0ull, c1 = 0ull, c2 = 0ull, c3 = 0ull;
        #pragma unroll
        for (int j = 0; j < 8; j += 2) {
            ulonglong2 ka = k2p[j];
            ulonglong2 kb = k2p[j + 1];
            c0 = fma2(q2[2 * j],     ka.x, c0);
            c1 = fma2(q2[2 * j + 1], ka.y, c1);
            c2 = fma2(q2[2 * j + 2], kb.x, c2);
            c3 = fma2(q2[2 * j + 3], kb.y, c3);
        }
        unsigned long long cs = add2(add2(c0, c1), add2(c2, c3));
        float alo, ahi;
        unpack2(alo, ahi, cs);
        float a = alo + ahi;
        if (feat && m >= PC) {
            int idx = tb - (int)fidx_s[m - PC];
            float badd = bt[idx];
            bool msk = (m < 32) ? ((mlo >> m) & 1u) : ((mhi >> (m - 32)) & 1u);
            a += msk ? (badd - 100.f) : badd;
        }
        const float e = __expf(a);
        sum += e;
        const unsigned long long e2 = pack2(e, e);
        const ulonglong2* v2p = (const ulonglong2*)(vs + m * HEADC);
        #pragma unroll
        for (int j = 0; j < 8; j++) {
            ulonglong2 vv = v2p[j];
            acc2[2 * j]     = fma2(e2, vv.x, acc2[2 * j]);
            acc2[2 * j + 1] = fma2(e2, vv.y, acc2[2 * j + 1]);
        }
    }

    const float inv = 1.0f / sum;
    const unsigned long long inv2 = pack2(inv, inv);

    uint2* op = g_attno_sp + (size_t)(base + t) * 48 + head * 16;
    #pragma unroll
    for (int j = 0; j < 16; j++) {
        unsigned long long r = mul2(acc2[j], inv2);
        float lo, hi;
        unpack2(lo, hi, r);
        op[j] = split_bf16_pair(lo, hi);
    }
}

// ---------------- launch ----------------
extern "C" void kernel_launch(void* const* d_in, const int* in_sizes, int n_in,
                              void* d_out, int out_size) {
    const float* x       = (const float*)d_in[0];
    const float* norm1_g = (const float*)d_in[1];
    const float* norm1_b = (const float*)d_in[2];
    const float* qkv_w   = (const float*)d_in[3];
    const float* qkv_b   = (const float*)d_in[4];
    const float* rpb     = (const float*)d_in[5];
    const float* proj_w  = (const float*)d_in[6];
    const float* proj_b  = (const float*)d_in[7];
    const float* norm2_g = (const float*)d_in[8];
    const float* norm2_b = (const float*)d_in[9];
    const float* fc1_w   = (const float*)d_in[10];
    const float* fc1_b   = (const float*)d_in[11];
    const float* fc2_w   = (const float*)d_in[12];
    const float* fc2_b   = (const float*)d_in[13];
    float* out = (float*)d_out;

    uint2 *p_attno, *p_wq, *p_wp, *p_w1, *p_w2;
    float *p_qkv, *p_y;
    cudaGetSymbolAddress((void**)&p_qkv,   g_qkv);
    cudaGetSymbolAddress((void**)&p_attno, g_attno_sp);
    cudaGetSymbolAddress((void**)&p_y,     g_y);
    cudaGetSymbolAddress((void**)&p_wq,    g_wq_sp);
    cudaGetSymbolAddress((void**)&p_wp,    g_wp_sp);
    cudaGetSymbolAddress((void**)&p_w1,    g_w1_sp);
    cudaGetSymbolAddress((void**)&p_w2,    g_w2_sp);

    cudaFuncSetAttribute(qkv_kernel, cudaFuncAttributeMaxDynamicSharedMemorySize, QKV_SMEM);
    cudaFuncSetAttribute(proj_gemm,  cudaFuncAttributeMaxDynamicSharedMemorySize, GEMM_SMEM);
    cudaFuncSetAttribute(fused_mlp_kernel, cudaFuncAttributeMaxDynamicSharedMemorySize, MLP_SMEM);

    // 0. pre-split weights
    split_w_kernel<<<216, 256>>>(qkv_w, proj_w, fc1_w, fc2_w);
    // 1+2. QKV GEMM with fused LN1 + window gather -> float
    qkv_kernel<<<MROWS / 64, 256, QKV_SMEM>>>(x, norm1_g, norm1_b, p_wq, qkv_b, p_qkv);
    // 3. windowed attention, single-pass streaming softmax (split out)
    attn_kernel<<<dim3(BATCHC * NWC, NHC), 64>>>(p_qkv, rpb);
    // 4. proj GEMM + scatter + residual-1 -> g_y
    proj_gemm<<<dim3(1, MROWS / 128), 256, GEMM_SMEM>>>(p_attno, p_wp, proj_b, x, p_y);
    // 5+6+7. fused MLP with fused LN2 + smem-residual: out = y + GELU(LN(y)@W1+b1)@W2+b2
    fused_mlp_kernel<<<MROWS / 64, 256, MLP_SMEM>>>(p_y, norm2_g, norm2_b,
                                                    p_w1, fc1_b, p_w2, fc2_b, out);
}

// round 17
// speedup vs baseline: 1.0544x; 1.0143x over previous
#include <cuda_runtime.h>
#include <cuda_bf16.h>
#include <math.h>

// ---------------- problem constants ----------------
#define DIMC    96
#define NHC     3
#define HEADC   32
#define WSC     7
#define SHIFTC  3
#define PC      5
#define HC      56
#define NWC     64
#define TPC     320
#define NNC     54
#define BATCHC  64
#define TOKC    3456
#define MROWS   (BATCHC * NWC * NNC)   // 221184
#define HIDC    384
#define SCALEC  0.17677669529663687f

// ---------------- scratch ----------------
__device__ float               g_qkv     [(size_t)MROWS * 3 * DIMC];
__device__ __align__(16) uint2 g_attno_sp[MROWS * 48];            // attn out, window order
__device__ float               g_y       [MROWS * DIMC];          // residual stream (fp32)
// pre-split weights [kpair][n]
__device__ __align__(16) uint2 g_wq_sp[48 * 288];
__device__ __align__(16) uint2 g_wp_sp[48 * 96];
__device__ __align__(16) uint2 g_w1_sp[48 * 384];
__device__ __align__(16) uint2 g_w2_sp[192 * 96];

__device__ __forceinline__ int map_token(int bw, int n) {
    int b = bw >> 6;
    int w = bw & 63;
    int tok;
    if (n < PC) {
        tok = w * PC + n;
    } else {
        int p  = n - PC;
        int r  = p / 7, c = p % 7;
        int wh = w >> 3, ww = w & 7;
        int hr = wh * 7 + r + SHIFTC; if (hr >= HC) hr -= HC;
        int wc = ww * 7 + c + SHIFTC; if (wc >= HC) wc -= HC;
        tok = TPC + hr * HC + wc;
    }
    return b * TOKC + tok;
}

__device__ __forceinline__ float warp_sum(float v) {
    #pragma unroll
    for (int o = 16; o; o >>= 1) v += __shfl_xor_sync(0xffffffffu, v, o);
    return v;
}

__device__ __forceinline__ uint2 split_bf16_pair(float x0, float x1) {
    __nv_bfloat16 h0 = __float2bfloat16(x0);
    __nv_bfloat16 h1 = __float2bfloat16(x1);
    float r0 = x0 - __bfloat162float(h0);
    float r1 = x1 - __bfloat162float(h1);
    __nv_bfloat16 l0 = __float2bfloat16(r0);
    __nv_bfloat16 l1 = __float2bfloat16(r1);
    uint2 o;
    o.x = ((unsigned)__bfloat16_as_ushort(h1) << 16) | (unsigned)__bfloat16_as_ushort(h0);
    o.y = ((unsigned)__bfloat16_as_ushort(l1) << 16) | (unsigned)__bfloat16_as_ushort(l0);
    return o;
}

// ---- packed f32x2 helpers ----
__device__ __forceinline__ unsigned long long pack2(float lo, float hi) {
    unsigned long long d;
    asm("mov.b64 %0, {%1, %2};" : "=l"(d) : "f"(lo), "f"(hi));
    return d;
}
__device__ __forceinline__ void unpack2(float& lo, float& hi, unsigned long long v) {
    asm("mov.b64 {%0, %1}, %2;" : "=f"(lo), "=f"(hi) : "l"(v));
}
__device__ __forceinline__ unsigned long long fma2(unsigned long long a, unsigned long long b,
                                                   unsigned long long c) {
    unsigned long long d;
    asm("fma.rn.f32x2 %0, %1, %2, %3;" : "=l"(d) : "l"(a), "l"(b), "l"(c));
    return d;
}
__device__ __forceinline__ unsigned long long add2(unsigned long long a, unsigned long long b) {
    unsigned long long d;
    asm("add.rn.f32x2 %0, %1, %2;" : "=l"(d) : "l"(a), "l"(b));
    return d;
}
__device__ __forceinline__ unsigned long long mul2(unsigned long long a, unsigned long long b) {
    unsigned long long d;
    asm("mul.rn.f32x2 %0, %1, %2;" : "=l"(d) : "l"(a), "l"(b));
    return d;
}

// ---------------- weight pre-split ----------------
__global__ __launch_bounds__(256)
void split_w_kernel(const float* __restrict__ qkv_w, const float* __restrict__ proj_w,
                    const float* __restrict__ fc1_w, const float* __restrict__ fc2_w) {
    int i = blockIdx.x * blockDim.x + threadIdx.x;
    if (i < 13824) {
        int kp = i / 288, n = i % 288;
        g_wq_sp[i] = split_bf16_pair(qkv_w[(2 * kp) * 288 + n], qkv_w[(2 * kp + 1) * 288 + n]);
    } else if (i < 18432) {
        int j = i - 13824, kp = j / 96, n = j % 96;
        g_wp_sp[j] = split_bf16_pair(proj_w[(2 * kp) * 96 + n], proj_w[(2 * kp + 1) * 96 + n]);
    } else if (i < 36864) {
        int j = i - 18432, kp = j / 384, n = j % 384;
        g_w1_sp[j] = split_bf16_pair(fc1_w[(2 * kp) * 384 + n], fc1_w[(2 * kp + 1) * 384 + n]);
    } else if (i < 55296) {
        int j = i - 36864, kp = j / 96, n = j % 96;
        g_w2_sp[j] = split_bf16_pair(fc2_w[(2 * kp) * 96 + n], fc2_w[(2 * kp + 1) * 96 + n]);
    }
}

// ---------------- BF16x3 MMA primitive ----------------
__device__ __forceinline__ void mma16(float c[4],
                                      unsigned a0, unsigned a1, unsigned a2, unsigned a3,
                                      unsigned b0, unsigned b1) {
    asm volatile("mma.sync.aligned.m16n8k16.row.col.f32.bf16.bf16.f32 "
                 "{%0,%1,%2,%3}, {%4,%5,%6,%7}, {%8,%9}, {%0,%1,%2,%3};\n"
                 : "+f"(c[0]), "+f"(c[1]), "+f"(c[2]), "+f"(c[3])
                 : "r"(a0), "r"(a1), "r"(a2), "r"(a3), "r"(b0), "r"(b1));
}

// LN a 64-row fp32 smem tile [64][100] into split pairs AsF[kpair][row]. 8 warps x 8 rows.
__device__ __forceinline__ void ln_tile_to_asf(const float* ytmp, uint2 (*AsF)[68],
                                               const float* __restrict__ lng,
                                               const float* __restrict__ lnb,
                                               int wid, int lane) {
    const float2* g2 = (const float2*)lng;
    const float2* b2 = (const float2*)lnb;
    float2 G0 = g2[lane], B0 = b2[lane];
    float2 G1 = make_float2(0.f, 0.f), B1 = make_float2(0.f, 0.f);
    if (lane < 16) { G1 = g2[32 + lane]; B1 = b2[32 + lane]; }
    #pragma unroll
    for (int rr = 0; rr < 8; rr++) {
        int r = wid * 8 + rr;
        float2 a0 = *(const float2*)&ytmp[r * 100 + 2 * lane];
        float2 a1 = make_float2(0.f, 0.f);
        if (lane < 16) a1 = *(const float2*)&ytmp[r * 100 + 64 + 2 * lane];
        float s = a0.x + a0.y + a1.x + a1.y;
        float mean = warp_sum(s) * (1.f / 96.f);
        float d0x = a0.x - mean, d0y = a0.y - mean;
        float d1x = a1.x - mean, d1y = a1.y - mean;
        float vq = d0x * d0x + d0y * d0y + (lane < 16 ? d1x * d1x + d1y * d1y : 0.f);
        float var = warp_sum(vq) * (1.f / 96.f);
        float inv = rsqrtf(var + 1e-5f);
        AsF[lane][r] = split_bf16_pair(d0x * inv * G0.x + B0.x, d0y * inv * G0.y + B0.y);
        if (lane < 16)
            AsF[32 + lane][r] = split_bf16_pair(d1x * inv * G1.x + B1.x, d1y * inv * G1.y + B1.y);
    }
}

// ---------------- QKV GEMM with fused LN1 + shifted-window gather ----------------
#define QKV_ASF  (48 * 68)
#define QKV_BS   (48 * 100)
#define QKV_SMEM ((QKV_ASF + QKV_BS) * 8)   // 64512 bytes

__global__ __launch_bounds__(256, 3)
void qkv_kernel(const float* __restrict__ x,
                const float* __restrict__ lng, const float* __restrict__ lnb,
                const uint2* __restrict__ W,
                const float* __restrict__ bias,
                float* __restrict__ out) {
    extern __shared__ uint2 smemu[];
    uint2 (*AsF)[68] = reinterpret_cast<uint2(*)[68]>(smemu);
    uint2 (*Bs)[100] = reinterpret_cast<uint2(*)[100]>(smemu + QKV_ASF);
    float* ytmp = (float*)(smemu + QKV_ASF);   // aliases Bs region (25.6 KB <= 38.4 KB)
    __shared__ int toks[64];

    const int tid  = threadIdx.x;
    const int wid  = tid >> 5, lane = tid & 31;
    const int gid  = lane >> 2, tig = lane & 3;
    const int wm   = (wid >> 2) * 32;
    const int wn   = (wid & 3) * 24;
    const int m0   = blockIdx.x * 64;

    // ---- prologue: gather x rows (float4), LN1, write split pairs into AsF ----
    if (tid < 64) {
        int r = m0 + tid;
        toks[tid] = map_token(r / NNC, r % NNC);
    }
    __syncthreads();
    #pragma unroll
    for (int j = 0; j < 6; j++) {                  // 64 rows x 24 float4
        int c   = tid + 256 * j;
        int row = c / 24, q4 = c % 24;
        float4 v = *((const float4*)(x + (size_t)toks[row] * DIMC) + q4);
        *(float4*)&ytmp[row * 100 + q4 * 4] = v;
    }
    __syncthreads();
    ln_tile_to_asf(ytmp, AsF, lng, lnb, wid, lane);

    for (int cc = 0; cc < 3; cc++) {
        __syncthreads();   // LN done for all warps (cc=0) / Bs reads done (cc>0)

        #pragma unroll
        for (int j = 0; j < 9; j++) {
            int c2 = tid + 256 * j;
            int kp = c2 / 48;
            int n2 = (c2 % 48) * 2;
            uint4 v = *(const uint4*)(W + (size_t)kp * 288 + cc * 96 + n2);
            *(uint4*)&Bs[kp][n2] = v;
        }
        __syncthreads();

        float acc[2][3][4];
        #pragma unroll
        for (int i = 0; i < 2; i++)
            #pragma unroll
            for (int j = 0; j < 3; j++)
                #pragma unroll
                for (int r = 0; r < 4; r++) acc[i][j][r] = 0.f;

        #pragma unroll
        for (int kt = 0; kt < 6; kt++) {
            const int kb = kt * 8;
            uint2 af[2][4];
            #pragma unroll
            for (int mt = 0; mt < 2; mt++) {
                const int m = wm + mt * 16 + gid;
                af[mt][0] = AsF[kb + tig    ][m];
                af[mt][1] = AsF[kb + tig    ][m + 8];
                af[mt][2] = AsF[kb + tig + 4][m];
                af[mt][3] = AsF[kb + tig + 4][m + 8];
            }
            uint2 bf[3][2];
            #pragma unroll
            for (int nt = 0; nt < 3; nt++) {
                const int n = wn + nt * 8 + gid;
                bf[nt][0] = Bs[kb + tig    ][n];
                bf[nt][1] = Bs[kb + tig + 4][n];
            }
            #pragma unroll
            for (int mt = 0; mt < 2; mt++)
                #pragma unroll
                for (int nt = 0; nt < 3; nt++) {
                    float* c = acc[mt][nt];
                    mma16(c, af[mt][0].x, af[mt][1].x, af[mt][2].x, af[mt][3].x,
                             bf[nt][0].x, bf[nt][1].x);
                    mma16(c, af[mt][0].x, af[mt][1].x, af[mt][2].x, af[mt][3].x,
                             bf[nt][0].y, bf[nt][1].y);
                    mma16(c, af[mt][0].y, af[mt][1].y, af[mt][2].y, af[mt][3].y,
                             bf[nt][0].x, bf[nt][1].x);
                }
        }

        float bb[3][2];
        #pragma unroll
        for (int nt = 0; nt < 3; nt++) {
            int c = cc * 96 + wn + nt * 8 + tig * 2;
            bb[nt][0] = bias[c];
            bb[nt][1] = bias[c + 1];
        }
        #pragma unroll
        for (int mt = 0; mt < 2; mt++) {
            #pragma unroll
            for (int half = 0; half < 2; half++) {
                size_t rg = (size_t)(m0 + wm + mt * 16 + gid + half * 8);
                float* op = out + rg * 288 + cc * 96 + wn + tig * 2;
                #pragma unroll
                for (int nt = 0; nt < 3; nt++) {
                    float v0 = acc[mt][nt][half * 2 + 0] + bb[nt][0];
                    float v1 = acc[mt][nt][half * 2 + 1] + bb[nt][1];
                    *(float2*)(op + nt * 8) = make_float2(v0, v1);
                }
            }
        }
    }
}

// ---------------- proj GEMM: 64-row blocks, K staged once, 3 CTAs/SM ----------------
#define PROJ_ASF  (48 * 68)
#define PROJ_BS   (48 * 100)
#define PROJ_SMEM ((PROJ_ASF + PROJ_BS) * 8)   // 64512 bytes

__global__ __launch_bounds__(256, 3)
void proj_gemm(const uint2* __restrict__ A, const uint2* __restrict__ Bw,
               const float* __restrict__ bias, const float* __restrict__ res,
               float* __restrict__ out) {
    extern __shared__ uint2 smemu[];
    uint2 (*AsF)[68] = reinterpret_cast<uint2(*)[68]>(smemu);
    uint2 (*Bs)[100] = reinterpret_cast<uint2(*)[100]>(smemu + PROJ_ASF);

    const int tid  = threadIdx.x;
    const int wid  = tid >> 5, lane = tid & 31;
    const int gid  = lane >> 2, tig = lane & 3;
    const int wm   = (wid >> 2) * 32;
    const int wn   = (wid & 3) * 24;
    const int m0   = blockIdx.x * 64;

    // stage A tile (64 rows x 48 kpairs) once
    #pragma unroll
    for (int j = 0; j < 6; j++) {
        int c   = tid + 256 * j;
        int row = c / 24;
        int kpp = (c % 24) * 2;
        uint4 v = *(const uint4*)(A + (size_t)(m0 + row) * 48 + kpp);
        AsF[kpp][row]     = make_uint2(v.x, v.y);
        AsF[kpp + 1][row] = make_uint2(v.z, v.w);
    }
    // stage full Wp (48 kp x 96 uint2 = 2304 uint4), same pattern as W-chunk loops
    #pragma unroll
    for (int j = 0; j < 9; j++) {
        int c2 = tid + 256 * j;
        int kp = c2 / 48;
        int n2 = (c2 % 48) * 2;
        uint4 v = *(const uint4*)(Bw + (size_t)kp * 96 + n2);
        *(uint4*)&Bs[kp][n2] = v;
    }
    __syncthreads();

    float acc[2][3][4];
    #pragma unroll
    for (int i = 0; i < 2; i++)
        #pragma unroll
        for (int j = 0; j < 3; j++)
            #pragma unroll
            for (int r = 0; r < 4; r++) acc[i][j][r] = 0.f;

    #pragma unroll
    for (int kt = 0; kt < 6; kt++) {
        const int kb = kt * 8;
        uint2 af[2][4];
        #pragma unroll
        for (int mt = 0; mt < 2; mt++) {
            const int m = wm + mt * 16 + gid;
            af[mt][0] = AsF[kb + tig    ][m];
            af[mt][1] = AsF[kb + tig    ][m + 8];
            af[mt][2] = AsF[kb + tig + 4][m];
            af[mt][3] = AsF[kb + tig + 4][m + 8];
        }
        uint2 bf[3][2];
        #pragma unroll
        for (int nt = 0; nt < 3; nt++) {
            const int n = wn + nt * 8 + gid;
            bf[nt][0] = Bs[kb + tig    ][n];
            bf[nt][1] = Bs[kb + tig + 4][n];
        }
        #pragma unroll
        for (int mt = 0; mt < 2; mt++)
            #pragma unroll
            for (int nt = 0; nt < 3; nt++) {
                float* c = acc[mt][nt];
                mma16(c, af[mt][0].x, af[mt][1].x, af[mt][2].x, af[mt][3].x,
                         bf[nt][0].x, bf[nt][1].x);
                mma16(c, af[mt][0].x, af[mt][1].x, af[mt][2].x, af[mt][3].x,
                         bf[nt][0].y, bf[nt][1].y);
                mma16(c, af[mt][0].y, af[mt][1].y, af[mt][2].y, af[mt][3].y,
                         bf[nt][0].x, bf[nt][1].x);
            }
    }

    float bb[3][2];
    #pragma unroll
    for (int nt = 0; nt < 3; nt++) {
        int c = wn + nt * 8 + tig * 2;
        bb[nt][0] = bias[c];
        bb[nt][1] = bias[c + 1];
    }
    #pragma unroll
    for (int mt = 0; mt < 2; mt++) {
        #pragma unroll
        for (int half = 0; half < 2; half++) {
            int r = m0 + wm + mt * 16 + gid + half * 8;
            size_t orow = (size_t)map_token(r / NNC, r % NNC);
            float*       op = out + orow * 96 + wn + tig * 2;
            const float* rp = res + orow * 96 + wn + tig * 2;
            #pragma unroll
            for (int nt = 0; nt < 3; nt++) {
                float v0 = acc[mt][nt][half * 2 + 0] + bb[nt][0] + rp[nt * 8];
                float v1 = acc[mt][nt][half * 2 + 1] + bb[nt][1] + rp[nt * 8 + 1];
                *(float2*)(op + nt * 8) = make_float2(v0, v1);
            }
        }
    }
}

// ---------------- fused MLP: LN2 prologue + residual-from-smem acc init ----------------
#define MLP_ASF  (48 * 68)
#define MLP_BS   (48 * 100)
#define MLP_HS   (48 * 68)
#define MLP_SMEM ((MLP_ASF + MLP_BS + MLP_HS) * 8)   // 90624 bytes

__global__ __launch_bounds__(256, 2)
void fused_mlp_kernel(const float* __restrict__ y,
                      const float* __restrict__ lng, const float* __restrict__ lnb,
                      const uint2* __restrict__ W1,
                      const float* __restrict__ b1,
                      const uint2* __restrict__ W2,
                      const float* __restrict__ b2,
                      float* __restrict__ out) {
    extern __shared__ uint2 smemu[];
    uint2 (*AsF)[68]  = reinterpret_cast<uint2(*)[68]>(smemu);
    uint2 (*Bs)[100]  = reinterpret_cast<uint2(*)[100]>(smemu + MLP_ASF);
    uint2 (*Hs)[68]   = reinterpret_cast<uint2(*)[68]>(smemu + MLP_ASF + MLP_BS);
    float* ytmp = (float*)(smemu + MLP_ASF + MLP_BS);   // aliases Hs

    const int tid  = threadIdx.x;
    const int wid  = tid >> 5, lane = tid & 31;
    const int gid  = lane >> 2, tig = lane & 3;
    const int wm   = (wid >> 2) * 32;
    const int wn   = (wid & 3) * 24;
    const int m0   = blockIdx.x * 64;

    #pragma unroll
    for (int j = 0; j < 6; j++) {
        int c   = tid + 256 * j;
        int row = c / 24, q4 = c % 24;
        float4 v = *((const float4*)(y + (size_t)(m0 + row) * DIMC) + q4);
        *(float4*)&ytmp[row * 100 + q4 * 4] = v;
    }
    __syncthreads();
    ln_tile_to_asf(ytmp, AsF, lng, lnb, wid, lane);

    float acc2[2][3][4];
    #pragma unroll
    for (int mt = 0; mt < 2; mt++) {
        #pragma unroll
        for (int half = 0; half < 2; half++) {
            int lr = wm + mt * 16 + gid + half * 8;
            #pragma unroll
            for (int nt = 0; nt < 3; nt++) {
                float2 rv = *(const float2*)&ytmp[lr * 100 + wn + tig * 2 + nt * 8];
                acc2[mt][nt][half * 2 + 0] = rv.x;
                acc2[mt][nt][half * 2 + 1] = rv.y;
            }
        }
    }

    for (int cc = 0; cc < 4; cc++) {
        __syncthreads();

        #pragma unroll
        for (int j = 0; j < 9; j++) {
            int c2 = tid + 256 * j;
            int kp = c2 / 48;
            int n2 = (c2 % 48) * 2;
            uint4 v = *(const uint4*)(W1 + (size_t)kp * 384 + cc * 96 + n2);
            *(uint4*)&Bs[kp][n2] = v;
        }
        __syncthreads();

        float acc1[2][3][4];
        #pragma unroll
        for (int i = 0; i < 2; i++)
            #pragma unroll
            for (int j = 0; j < 3; j++)
                #pragma unroll
                for (int r = 0; r < 4; r++) acc1[i][j][r] = 0.f;

        #pragma unroll
        for (int kt = 0; kt < 6; kt++) {
            const int kb = kt * 8;
            uint2 af[2][4];
            #pragma unroll
            for (int mt = 0; mt < 2; mt++) {
                const int m = wm + mt * 16 + gid;
                af[mt][0] = AsF[kb + tig    ][m];
                af[mt][1] = AsF[kb + tig    ][m + 8];
                af[mt][2] = AsF[kb + tig + 4][m];
                af[mt][3] = AsF[kb + tig + 4][m + 8];
            }
            uint2 bf[3][2];
            #pragma unroll
            for (int nt = 0; nt < 3; nt++) {
                const int n = wn + nt * 8 + gid;
                bf[nt][0] = Bs[kb + tig    ][n];
                bf[nt][1] = Bs[kb + tig + 4][n];
            }
            #pragma unroll
            for (int mt = 0; mt < 2; mt++)
                #pragma unroll
                for (int nt = 0; nt < 3; nt++) {
                    float* c = acc1[mt][nt];
                    mma16(c, af[mt][0].x, af[mt][1].x, af[mt][2].x, af[mt][3].x,
                             bf[nt][0].x, bf[nt][1].x);
                    mma16(c, af[mt][0].x, af[mt][1].x, af[mt][2].x, af[mt][3].x,
                             bf[nt][0].y, bf[nt][1].y);
                    mma16(c, af[mt][0].y, af[mt][1].y, af[mt][2].y, af[mt][3].y,
                             bf[nt][0].x, bf[nt][1].x);
                }
        }

        float bb1[3][2];
        #pragma unroll
        for (int nt = 0; nt < 3; nt++) {
            int c = cc * 96 + wn + nt * 8 + tig * 2;
            bb1[nt][0] = b1[c];
            bb1[nt][1] = b1[c + 1];
        }
        #pragma unroll
        for (int mt = 0; mt < 2; mt++) {
            #pragma unroll
            for (int half = 0; half < 2; half++) {
                int r = wm + mt * 16 + gid + half * 8;
                #pragma unroll
                for (int nt = 0; nt < 3; nt++) {
                    float v0 = acc1[mt][nt][half * 2 + 0] + bb1[nt][0];
                    float v1 = acc1[mt][nt][half * 2 + 1] + bb1[nt][1];
                    v0 = 0.5f * v0 * (1.0f + erff(v0 * 0.70710678118654752f));
                    v1 = 0.5f * v1 * (1.0f + erff(v1 * 0.70710678118654752f));
                    int p = (wn >> 1) + nt * 4 + tig;
                    Hs[p][r] = split_bf16_pair(v0, v1);
                }
            }
        }
        __syncthreads();

        #pragma unroll
        for (int j = 0; j < 9; j++) {
            int c2 = tid + 256 * j;
            int kp = c2 / 48;
            int n2 = (c2 % 48) * 2;
            uint4 v = *(const uint4*)(W2 + (size_t)(cc * 48 + kp) * 96 + n2);
            *(uint4*)&Bs[kp][n2] = v;
        }
        __syncthreads();

        #pragma unroll
        for (int kt = 0; kt < 6; kt++) {
            const int kb = kt * 8;
            uint2 af[2][4];
            #pragma unroll
            for (int mt = 0; mt < 2; mt++) {
                const int m = wm + mt * 16 + gid;
                af[mt][0] = Hs[kb + tig    ][m];
                af[mt][1] = Hs[kb + tig    ][m + 8];
                af[mt][2] = Hs[kb + tig + 4][m];
                af[mt][3] = Hs[kb + tig + 4][m + 8];
            }
            uint2 bf[3][2];
            #pragma unroll
            for (int nt = 0; nt < 3; nt++) {
                const int n = wn + nt * 8 + gid;
                bf[nt][0] = Bs[kb + tig    ][n];
                bf[nt][1] = Bs[kb + tig + 4][n];
            }
            #pragma unroll
            for (int mt = 0; mt < 2; mt++)
                #pragma unroll
                for (int nt = 0; nt < 3; nt++) {
                    float* c = acc2[mt][nt];
                    mma16(c, af[mt][0].x, af[mt][1].x, af[mt][2].x, af[mt][3].x,
                             bf[nt][0].x, bf[nt][1].x);
                    mma16(c, af[mt][0].x, af[mt][1].x, af[mt][2].x, af[mt][3].x,
                             bf[nt][0].y, bf[nt][1].y);
                    mma16(c, af[mt][0].y, af[mt][1].y, af[mt][2].y, af[mt][3].y,
                             bf[nt][0].x, bf[nt][1].x);
                }
        }
    }

    float bb2[3][2];
    #pragma unroll
    for (int nt = 0; nt < 3; nt++) {
        int c = wn + nt * 8 + tig * 2;
        bb2[nt][0] = b2[c];
        bb2[nt][1] = b2[c + 1];
    }
    #pragma unroll
    for (int mt = 0; mt < 2; mt++) {
        #pragma unroll
        for (int half = 0; half < 2; half++) {
            size_t rg = (size_t)(m0 + wm + mt * 16 + gid + half * 8);
            float* op = out + rg * 96 + wn + tig * 2;
            #pragma unroll
            for (int nt = 0; nt < 3; nt++) {
                float v0 = acc2[mt][nt][half * 2 + 0] + bb2[nt][0];
                float v1 = acc2[mt][nt][half * 2 + 1] + bb2[nt][1];
                *(float2*)(op + nt * 8) = make_float2(v0, v1);
            }
        }
    }
}

// ---------------- windowed attention: single-pass streaming softmax (unchanged) ----------------
__global__ __launch_bounds__(64, 8)
void attn_kernel(const float* __restrict__ qkv, const float* __restrict__ rpb) {
    __shared__ float ks[NNC * HEADC];
    __shared__ float vs[NNC * HEADC];
    __shared__ float bt[169];
    __shared__ unsigned char fidx_s[49];
    __shared__ int regn_s[NNC];

    const int bw   = blockIdx.x;
    const int head = blockIdx.y;
    const int base = bw * NNC;
    const int tid  = threadIdx.x;

    for (int idx = tid; idx < NNC * HEADC; idx += 64) {
        int m = idx >> 5, d = idx & 31;
        const float* p = qkv + (size_t)(base + m) * (3 * DIMC) + head * HEADC + d;
        ks[idx] = p[DIMC];
        vs[idx] = p[2 * DIMC];
    }
    for (int i = tid; i < 169; i += 64) bt[i] = rpb[i * NHC + head];
    if (tid < 49) fidx_s[tid] = (unsigned char)((tid / 7) * 13 + (tid % 7));
    if (tid < NNC) {
        int i = tid;
        if (i < PC) regn_s[i] = -1;
        else {
            int p = i - PC;
            int r = p / 7, c = p % 7;
            int w = bw & 63;
            int gh = (w >> 3) * 7 + r;
            int gw = (w & 7) * 7 + c;
            int rh = gh < 49 ? 0 : (gh < 53 ? 1 : 2);
            int rw = gw < 49 ? 0 : (gw < 53 ? 1 : 2);
            regn_s[i] = rh * 3 + rw;
        }
    }
    __syncthreads();

    const int t = tid;
    if (t >= NNC) return;

    const ulonglong2* qp2 = (const ulonglong2*)(qkv + (size_t)(base + t) * (3 * DIMC) + head * HEADC);
    const unsigned long long sc2 = pack2(SCALEC, SCALEC);
    unsigned long long q2[16];
    #pragma unroll
    for (int j = 0; j < 8; j++) {
        ulonglong2 qq = qp2[j];
        q2[2 * j]     = mul2(qq.x, sc2);
        q2[2 * j + 1] = mul2(qq.y, sc2);
    }

    const bool feat = (t >= PC);
    int tb = 0;
    unsigned mlo = 0, mhi = 0;
    if (feat) {
        int p = t - PC;
        tb = (p / 7 + 6) * 13 + (p % 7 + 6);
        int myreg = regn_s[t];
        #pragma unroll 7
        for (int m = PC; m < NNC; m++) {
            if (regn_s[m] != myreg) {
                if (m < 32) mlo |= 1u << m;
                else        mhi |= 1u << (m - 32);
            }
        }
    }

    unsigned long long acc2[16];
    #pragma unroll
    for (int j = 0; j < 16; j++) acc2[j] = 0ull;
    float sum = 0.f;

    #pragma unroll 3
    for (int m = 0; m < NNC; m++) {
        const ulonglong2* k2p = (const ulonglong2*)(ks + m * HEADC);
        unsigned long long c0 = 0ull, c1 = 0ull, c2 = 0ull, c3 = 0ull;
        #pragma unroll
        for (int j = 0; j < 8; j += 2) {
            ulonglong2 ka = k2p[j];
            ulonglong2 kb = k2p[j + 1];
            c0 = fma2(q2[2 * j],     ka.x, c0);
            c1 = fma2(q2[2 * j + 1], ka.y, c1);
            c2 = fma2(q2[2 * j + 2], kb.x, c2);
            c3 = fma2(q2[2 * j + 3], kb.y, c3);
        }
        unsigned long long cs = add2(add2(c0, c1), add2(c2, c3));
        float alo, ahi;
        unpack2(alo, ahi, cs);
        float a = alo + ahi;
        if (feat && m >= PC) {
            int idx = tb - (int)fidx_s[m - PC];
            float badd = bt[idx];
            bool msk = (m < 32) ? ((mlo >> m) & 1u) : ((mhi >> (m - 32)) & 1u);
            a += msk ? (badd - 100.f) : badd;
        }
        const float e = __expf(a);
        sum += e;
        const unsigned long long e2 = pack2(e, e);
        const ulonglong2* v2p = (const ulonglong2*)(vs + m * HEADC);
        #pragma unroll
        for (int j = 0; j < 8; j++) {
            ulonglong2 vv = v2p[j];
            acc2[2 * j]     = fma2(e2, vv.x, acc2[2 * j]);
            acc2[2 * j + 1] = fma2(e2, vv.y, acc2[2 * j + 1]);
        }
    }

    const float inv = 1.0f / sum;
    const unsigned long long inv2 = pack2(inv, inv);

    uint2* op = g_attno_sp + (size_t)(base + t) * 48 + head * 16;
    #pragma unroll
    for (int j = 0; j < 16; j++) {
        unsigned long long r = mul2(acc2[j], inv2);
        float lo, hi;
        unpack2(lo, hi, r);
        op[j] = split_bf16_pair(lo, hi);
    }
}

// ---------------- launch ----------------
extern "C" void kernel_launch(void* const* d_in, const int* in_sizes, int n_in,
                              void* d_out, int out_size) {
    const float* x       = (const float*)d_in[0];
    const float* norm1_g = (const float*)d_in[1];
    const float* norm1_b = (const float*)d_in[2];
    const float* qkv_w   = (const float*)d_in[3];
    const float* qkv_b   = (const float*)d_in[4];
    const float* rpb     = (const float*)d_in[5];
    const float* proj_w  = (const float*)d_in[6];
    const float* proj_b  = (const float*)d_in[7];
    const float* norm2_g = (const float*)d_in[8];
    const float* norm2_b = (const float*)d_in[9];
    const float* fc1_w   = (const float*)d_in[10];
    const float* fc1_b   = (const float*)d_in[11];
    const float* fc2_w   = (const float*)d_in[12];
    const float* fc2_b   = (const float*)d_in[13];
    float* out = (float*)d_out;

    uint2 *p_attno, *p_wq, *p_wp, *p_w1, *p_w2;
    float *p_qkv, *p_y;
    cudaGetSymbolAddress((void**)&p_qkv,   g_qkv);
    cudaGetSymbolAddress((void**)&p_attno, g_attno_sp);
    cudaGetSymbolAddress((void**)&p_y,     g_y);
    cudaGetSymbolAddress((void**)&p_wq,    g_wq_sp);
    cudaGetSymbolAddress((void**)&p_wp,    g_wp_sp);
    cudaGetSymbolAddress((void**)&p_w1,    g_w1_sp);
    cudaGetSymbolAddress((void**)&p_w2,    g_w2_sp);

    cudaFuncSetAttribute(qkv_kernel, cudaFuncAttributeMaxDynamicSharedMemorySize, QKV_SMEM);
    cudaFuncSetAttribute(proj_gemm,  cudaFuncAttributeMaxDynamicSharedMemorySize, PROJ_SMEM);
    cudaFuncSetAttribute(fused_mlp_kernel, cudaFuncAttributeMaxDynamicSharedMemorySize, MLP_SMEM);

    // 0. pre-split weights
    split_w_kernel<<<216, 256>>>(qkv_w, proj_w, fc1_w, fc2_w);
    // 1+2. QKV GEMM with fused LN1 + window gather -> float
    qkv_kernel<<<MROWS / 64, 256, QKV_SMEM>>>(x, norm1_g, norm1_b, p_wq, qkv_b, p_qkv);
    // 3. windowed attention, single-pass streaming softmax (split out)
    attn_kernel<<<dim3(BATCHC * NWC, NHC), 64>>>(p_qkv, rpb);
    // 4. proj GEMM + scatter + residual-1 -> g_y  (64-row blocks, 3 CTAs/SM)
    proj_gemm<<<MROWS / 64, 256, PROJ_SMEM>>>(p_attno, p_wp, proj_b, x, p_y);
    // 5+6+7. fused MLP with fused LN2 + smem-residual
    fused_mlp_kernel<<<MROWS / 64, 256, MLP_SMEM>>>(p_y, norm2_g, norm2_b,
                                                    p_w1, fc1_b, p_w2, fc2_b, out);
}